// round 14
// baseline (speedup 1.0000x reference)
#include <cuda_runtime.h>
#include <math.h>
#include <stdint.h>

// Problem constants
#define BQ   2
#define TSEQ 2048
#define DMODEL 2048
#define NH   16
#define NKV  8
#define DH   128
#define MROWS (BQ*TSEQ)   // 4096

// ---------------- device scratch ----------------------------------------------
__device__ float g_qkv[MROWS * 4096];         // q(2048) | k(1024) | v(1024)
// g_q/g_k: [B,H,T,DH] with d-words permuted within 8-blocks: pos = 2*(d&3) + ((d>>2)&1)
__device__ float g_q  [BQ * NH  * TSEQ * DH]; // tf32 bits, pre-scaled by 1/sqrt(128)
__device__ float g_k  [BQ * NKV * TSEQ * DH]; // tf32 bits
// g_v: [B,Hkv] pair-grouped: word ((t>>3)*4 + (t&3))*256 + d*2 + ((t>>2)&1)
__device__ float g_v  [BQ * NKV * TSEQ * DH]; // tf32 bits
__device__ float g_ctx[MROWS * DMODEL];
__device__ float g_cos[TSEQ * 64];
__device__ float g_sin[TSEQ * 64];

// ---------------- helpers -----------------------------------------------------
__device__ __forceinline__ uint32_t f2tf32(float f) {
    uint32_t u;
    asm("cvt.rna.tf32.f32 %0, %1;" : "=r"(u) : "f"(f));
    return u;
}
__device__ __forceinline__ uint32_t smem_u32(const void* p) {
    uint32_t a;
    asm("{ .reg .u64 t; cvta.to.shared.u64 t, %1; cvt.u32.u64 %0, t; }" : "=r"(a) : "l"(p));
    return a;
}
// D += A(m16k8 row) * B(k8n8 col), tf32
__device__ __forceinline__ void mma8(float* d, const uint32_t* a, const uint32_t* b) {
    asm volatile(
        "mma.sync.aligned.m16n8k8.row.col.f32.tf32.tf32.f32 "
        "{%0,%1,%2,%3}, {%4,%5,%6,%7}, {%8,%9}, {%0,%1,%2,%3};"
        : "+f"(d[0]), "+f"(d[1]), "+f"(d[2]), "+f"(d[3])
        : "r"(a[0]), "r"(a[1]), "r"(a[2]), "r"(a[3]), "r"(b[0]), "r"(b[1]));
}
#define CPA16(dst, src) asm volatile("cp.async.cg.shared.global [%0], [%1], 16;" :: "r"(dst), "l"(src) : "memory")
#define CPC()   asm volatile("cp.async.commit_group;" ::: "memory")
#define CPW0()  asm volatile("cp.async.wait_group 0;" ::: "memory")
#define CPW1()  asm volatile("cp.async.wait_group 1;" ::: "memory")
#define CPW2()  asm volatile("cp.async.wait_group 2;" ::: "memory")
#define PAIRBAR(id) asm volatile("bar.sync %0, 64;" :: "r"(id) : "memory")
#define STS128(addr, v0, v1, v2, v3) \
    asm volatile("st.shared.v4.b32 [%0], {%1,%2,%3,%4};" \
                 :: "r"(addr), "r"(v0), "r"(v1), "r"(v2), "r"(v3) : "memory")

// fast exp on the fma/alu pipes: x <= 0 expected
__device__ __forceinline__ float expf_fast(float x) {
    float z = x * 1.4426950408889634f;
    z = fmaxf(z, -126.0f);
    float r = z + 12582912.0f;                       // round-to-nearest integer
    int   i = __float_as_int(r) - 0x4B400000;
    float f = z - (r - 12582912.0f);                 // f in [-0.5, 0.5]
    float p = fmaf(f, 0.0013333558f, 0.0096181291f); // 2^f poly (deg 5)
    p = fmaf(f, p, 0.0555041087f);
    p = fmaf(f, p, 0.2402265069f);
    p = fmaf(f, p, 0.6931471806f);
    p = fmaf(f, p, 1.0f);
    return __int_as_float(__float_as_int(p) + (i << 23));
}

// ---------------- RoPE table --------------------------------------------------
__global__ void build_rope_kernel() {
    int t = blockIdx.x;
    int i = threadIdx.x;  // 0..63
    double inv = exp(-((double)(2 * i) / 128.0) * log(1.0e6));
    float af = (float)((double)t * inv);
    g_cos[t * 64 + i] = cosf(af);
    g_sin[t * 64 + i] = sinf(af);
}

// ---------------- TF32 GEMM: C[m,n] = A[M,K] @ W[N,K]^T -----------------------
// 256x128 tile, BK=16, 4-stage cp.async, 512 threads (16 warps), warp tile 64x32.
#define GBM 256
#define GBN 128
#define GBK 16
#define GP  20
#define GSTG 4
#define GA_WORDS (GBM * GP)
#define GB_WORDS (GBN * GP)
#define GSTG_WORDS (GA_WORDS + GB_WORDS)
#define GEMM_SMEM (GSTG * GSTG_WORDS * 4)

__global__ __launch_bounds__(512, 1) void gemm_kernel(
    const float* __restrict__ A, const float* __restrict__ W0,
    const float* __restrict__ W1, const float* __restrict__ W2,
    int ns1, int ns2, float* __restrict__ C, int ldc)
{
    extern __shared__ float gs[];
    const int tid = threadIdx.x, lane = tid & 31, wid = tid >> 5;
    const int gid = lane >> 2, tig = lane & 3;
    const int wm = (wid & 3) * 64, wn = (wid >> 2) * 32;
    const int m0 = blockIdx.y * GBM;
    const int n0 = blockIdx.x * GBN;
    const int K = DMODEL;

    const float* Bw; int nb;
    if (n0 < ns1)      { Bw = W0; nb = n0; }
    else if (n0 < ns2) { Bw = W1; nb = n0 - ns1; }
    else               { Bw = W2; nb = n0 - ns2; }

    // loaders: A row tid>>1, half (tid&1)*8 (2 chunks); B row tid>>2, (tid&3)*4 (1 chunk)
    const int arow = tid >> 1, akseg = (tid & 1) * 8;
    const int brow = tid >> 2, bkseg = (tid & 3) * 4;
    const float* asrc = A  + (size_t)(m0 + arow) * K + akseg;
    const float* bsrc = Bw + (size_t)(nb + brow) * K + bkseg;
    const uint32_t smb = smem_u32(gs);
    const uint32_t adst = smb + (arow * GP + akseg) * 4;
    const uint32_t bdst = smb + (GA_WORDS + brow * GP + bkseg) * 4;

    const int niter = K / GBK;  // 128

    #pragma unroll
    for (int s = 0; s < GSTG - 1; s++) {
        const int k0 = s * GBK;
        const uint32_t so = s * GSTG_WORDS * 4;
        CPA16(adst + so,      asrc + k0);
        CPA16(adst + so + 16, asrc + k0 + 4);
        CPA16(bdst + so,      bsrc + k0);
        CPC();
    }

    float acc[4][4][4];
    #pragma unroll
    for (int mt = 0; mt < 4; mt++)
        #pragma unroll
        for (int nt = 0; nt < 4; nt++)
            #pragma unroll
            for (int r = 0; r < 4; r++) acc[mt][nt][r] = 0.f;

    for (int kt = 0; kt < niter; kt++) {
        if (kt + 3 <= niter) { CPW2(); }
        else if (kt + 2 == niter) { CPW1(); }
        else { CPW0(); }
        __syncthreads();

        if (kt + 3 < niter) {
            const int k0 = (kt + 3) * GBK;
            const uint32_t so = ((kt + 3) & 3) * GSTG_WORDS * 4;
            CPA16(adst + so,      asrc + k0);
            CPA16(adst + so + 16, asrc + k0 + 4);
            CPA16(bdst + so,      bsrc + k0);
            CPC();
        }

        const float* sa = gs + (kt & 3) * GSTG_WORDS;
        const float* sb = sa + GA_WORDS;
        #pragma unroll
        for (int ks = 0; ks < 2; ks++) {
            uint32_t af[4][4], bf[4][2];
            #pragma unroll
            for (int mt = 0; mt < 4; mt++) {
                int base = (wm + mt * 16 + gid) * GP + ks * 8 + tig;
                af[mt][0] = f2tf32(sa[base]);
                af[mt][1] = f2tf32(sa[base + 8 * GP]);
                af[mt][2] = f2tf32(sa[base + 4]);
                af[mt][3] = f2tf32(sa[base + 8 * GP + 4]);
            }
            #pragma unroll
            for (int nt = 0; nt < 4; nt++) {
                int base = (wn + nt * 8 + gid) * GP + ks * 8 + tig;
                bf[nt][0] = f2tf32(sb[base]);
                bf[nt][1] = f2tf32(sb[base + 4]);
            }
            #pragma unroll
            for (int mt = 0; mt < 4; mt++)
                #pragma unroll
                for (int nt = 0; nt < 4; nt++)
                    mma8(acc[mt][nt], af[mt], bf[nt]);
        }
    }

    #pragma unroll
    for (int mt = 0; mt < 4; mt++) {
        #pragma unroll
        for (int nt = 0; nt < 4; nt++) {
            int r0 = m0 + wm + mt * 16 + gid;
            int c0 = n0 + wn + nt * 8 + tig * 2;
            *(float2*)&C[(size_t)r0 * ldc + c0]       = make_float2(acc[mt][nt][0], acc[mt][nt][1]);
            *(float2*)&C[(size_t)(r0 + 8) * ldc + c0] = make_float2(acc[mt][nt][2], acc[mt][nt][3]);
        }
    }
}

// ---------------- RMSNorm + RoPE (warp per head), permuted stores -------------
__global__ __launch_bounds__(256) void qkv_postprocess_kernel(
    const float* __restrict__ qnw, const float* __restrict__ knw)
{
    const int lane = threadIdx.x & 31;
    const int hidx = blockIdx.x * 8 + (threadIdx.x >> 5);
    const int tg = hidx >> 5;            // b*T + t
    const int hh = hidx & 31;
    const int b = tg / TSEQ;
    const int t = tg - b * TSEQ;

    const float* src;
    float* dst;
    const float* w = qnw;
    bool isv = false;
    float outscale = 0.08838834764831845f;
    if (hh < NH) {
        src = g_qkv + (size_t)tg * 4096 + hh * DH;
        dst = g_q + ((size_t)(b * NH + hh) * TSEQ + t) * DH;
    } else if (hh < NH + NKV) {
        int h = hh - NH;
        src = g_qkv + (size_t)tg * 4096 + 2048 + h * DH;
        w = knw;
        outscale = 1.0f;
        dst = g_k + ((size_t)(b * NKV + h) * TSEQ + t) * DH;
    } else {
        int h = hh - NH - NKV;
        src = g_qkv + (size_t)tg * 4096 + 3072 + h * DH;
        dst = g_v + (size_t)(b * NKV + h) * (TSEQ * DH)
                  + ((size_t)((t >> 3) * 4 + (t & 3))) * 256 + ((t >> 2) & 1);
        isv = true;
    }

    const int d0 = lane * 4;
    float4 x = *(const float4*)(src + d0);

    if (isv) {
        dst[(d0 + 0) * 2] = __uint_as_float(f2tf32(x.x));
        dst[(d0 + 1) * 2] = __uint_as_float(f2tf32(x.y));
        dst[(d0 + 2) * 2] = __uint_as_float(f2tf32(x.z));
        dst[(d0 + 3) * 2] = __uint_as_float(f2tf32(x.w));
        return;
    }

    float ss = x.x * x.x + x.y * x.y + x.z * x.z + x.w * x.w;
    #pragma unroll
    for (int o = 16; o > 0; o >>= 1) ss += __shfl_xor_sync(0xffffffffu, ss, o);
    const float rms = rsqrtf(ss * (1.0f / 128.0f) + 1e-6f);

    float4 wv = *(const float4*)(w + d0);
    float4 nx;
    nx.x = x.x * rms * wv.x; nx.y = x.y * rms * wv.y;
    nx.z = x.z * rms * wv.z; nx.w = x.w * rms * wv.w;

    float4 pn;
    pn.x = __shfl_xor_sync(0xffffffffu, nx.x, 16);
    pn.y = __shfl_xor_sync(0xffffffffu, nx.y, 16);
    pn.z = __shfl_xor_sync(0xffffffffu, nx.z, 16);
    pn.w = __shfl_xor_sync(0xffffffffu, nx.w, 16);
    const float sgn = (lane < 16) ? -1.0f : 1.0f;

    const int i0 = d0 & 63;
    float4 c4 = *(const float4*)(g_cos + t * 64 + i0);
    float4 s4 = *(const float4*)(g_sin + t * 64 + i0);

    float o0 = (nx.x * c4.x + sgn * pn.x * s4.x) * outscale;
    float o1 = (nx.y * c4.y + sgn * pn.y * s4.y) * outscale;
    float o2 = (nx.z * c4.z + sgn * pn.z * s4.z) * outscale;
    float o3 = (nx.w * c4.w + sgn * pn.w * s4.w) * outscale;

    float* pd = dst + (lane >> 1) * 8 + (lane & 1);
    pd[0] = __uint_as_float(f2tf32(o0));
    pd[2] = __uint_as_float(f2tf32(o1));
    pd[4] = __uint_as_float(f2tf32(o2));
    pd[6] = __uint_as_float(f2tf32(o3));
}

// ---------------- Flash attention v6: 128q tile, d-split pairs, P via smem ----
#define FQ_OFF  0
#define FK_OFF  17408                 // Q: 128*136
#define FV_OFF  (FK_OFF + 8704)      // K: 64*136
#define FP_OFF  (FV_OFF + 8448)      // V: 32*264
#define FEX_OFF (FP_OFF + 8704)      // P: 8 pairs * 8 * 136
#define FLASH_WORDS (FEX_OFF + 512)
#define FLASH_SMEM (FLASH_WORDS * 4) // 175104 B

__global__ __launch_bounds__(512, 1) void flash_attn_kernel() {
    extern __shared__ float fsm[];
    const uint2* Q2 = (const uint2*)fsm;                 // pitch 68 uint2
    const uint2* K2 = (const uint2*)(fsm + FK_OFF);
    const uint2* V2 = (const uint2*)(fsm + FV_OFF);
    const uint2* P2 = (const uint2*)(fsm + FP_OFF);
    float* sMax = fsm + FEX_OFF;        // [2][128]
    float* sSum = fsm + FEX_OFF + 256;  // [2][128]

    const int tid  = threadIdx.x;
    const int lane = tid & 31;
    const int wid  = tid >> 5;           // 0..15
    const int gid  = lane >> 2;
    const int tig  = lane & 3;
    const int pair = wid & 7;
    const int role = wid >> 3;           // 0/1: k-half in S, d-half in PV
    const int wm   = pair * 16;
    const int kh   = role * 32;
    const int barid = pair + 1;

    const int bh = blockIdx.y;
    const int b = bh >> 4;
    const int h = bh & 15;
    const int hk = h >> 1;
    const int q0 = (15 - (int)blockIdx.x) * 128;   // big blocks first
    const int ntiles = (q0 >> 6) + 2;

    const float* Qg = g_q + ((size_t)(b * NH + h) * TSEQ + q0) * DH;
    const float* Kg = g_k + (size_t)(b * NKV + hk) * TSEQ * DH;
    const float* Vg = g_v + (size_t)(b * NKV + hk) * (TSEQ * DH);

    // cp.async loader geometry (512 threads)
    const uint32_t smb = smem_u32(fsm);
    const int qr = tid >> 2, qs = (tid & 3) * 32;        // Q: 128 rows
    const uint32_t qdst = smb + (qr * 136 + qs) * 4;
    const float* qsrc = Qg + (size_t)qr * DH + qs;
    const int kr = tid >> 3, ksg = (tid & 7) * 16;       // K: 64 rows
    const uint32_t kdst = smb + (FK_OFF + kr * 136 + ksg) * 4;
    const float* ksrc = Kg + (size_t)kr * DH + ksg;
    const int vgr = tid >> 4, vsg = (tid & 15) * 16;     // V: 32 groups
    const uint32_t vdst = smb + (FV_OFF + vgr * 264 + vsg) * 4;
    const float* vsrc = Vg + vgr * 256 + vsg;

    // prologue: {Q + K[0]} group, {V[0]} group
    #pragma unroll
    for (int c = 0; c < 8; c++) CPA16(qdst + c * 16, qsrc + c * 4);
    #pragma unroll
    for (int c = 0; c < 4; c++) CPA16(kdst + c * 16, ksrc + c * 4);
    CPC();
    #pragma unroll
    for (int c = 0; c < 4; c++) CPA16(vdst + c * 16, vsrc + c * 4);
    CPC();

    float acc[8][4];                      // PV for own d-half (full k)
    #pragma unroll
    for (int nt = 0; nt < 8; nt++)
        #pragma unroll
        for (int r = 0; r < 4; r++) acc[nt][r] = 0.f;
    float m0r = -INFINITY, m1r = -INFINITY, l0r = 0.f, l1r = 0.f;

    const int pr0 = wm + gid, pr1 = pr0 + 8;   // pair-local q rows (block view)

    for (int j = 0; j < ntiles; j++) {
        const int k0 = j * 64;
        const bool more = (j + 1 < ntiles);
        const bool active = (q0 + wm + 15) >= k0;

        CPW1();                  // K[j] (+Q) resident; V[j] may be pending
        __syncthreads();

        // ---- S = Q @ K^T over own k-half (16 x 32) ----
        float sacc[4][4];
        #pragma unroll
        for (int nt = 0; nt < 4; nt++)
            #pragma unroll
            for (int r = 0; r < 4; r++) sacc[nt][r] = 0.f;

        if (active) {
            #pragma unroll
            for (int ks = 0; ks < 16; ks++) {
                uint32_t af[4];
                const int qo = ((wm + gid) * 136 + ks * 8 + tig * 2) >> 1;
                uint2 qa = Q2[qo];
                uint2 qb = Q2[qo + 8 * 68];
                af[0] = qa.x; af[2] = qa.y;
                af[1] = qb.x; af[3] = qb.y;
                #pragma unroll
                for (int nt = 0; nt < 4; nt++) {
                    uint2 kb2 = K2[((kh + nt * 8 + gid) * 136 + ks * 8 + tig * 2) >> 1];
                    uint32_t bfr[2] = {kb2.x, kb2.y};
                    mma8(sacc[nt], af, bfr);
                }
            }
        }
        __syncthreads();         // K consumed by all

        if (more) {
            const float* ks2 = ksrc + (size_t)(k0 + 64) * DH;
            #pragma unroll
            for (int c = 0; c < 4; c++) CPA16(kdst + c * 16, ks2 + c * 4);
            CPC();
        }

        if (active) {
            // ---- mask near-diagonal tiles ----
            const int off = q0 - k0;    // mask if local col c0 > off + row
            if (off < 64) {
                #pragma unroll
                for (int nt = 0; nt < 4; nt++) {
                    int c0 = kh + nt * 8 + tig * 2;
                    if (c0     > off + pr0) sacc[nt][0] = -1e30f;
                    if (c0 + 1 > off + pr0) sacc[nt][1] = -1e30f;
                    if (c0     > off + pr1) sacc[nt][2] = -1e30f;
                    if (c0 + 1 > off + pr1) sacc[nt][3] = -1e30f;
                }
            }

            // ---- partial max + pair exchange ----
            float mx0 = -INFINITY, mx1 = -INFINITY;
            #pragma unroll
            for (int nt = 0; nt < 4; nt++) {
                mx0 = fmaxf(mx0, fmaxf(sacc[nt][0], sacc[nt][1]));
                mx1 = fmaxf(mx1, fmaxf(sacc[nt][2], sacc[nt][3]));
            }
            mx0 = fmaxf(mx0, __shfl_xor_sync(0xffffffffu, mx0, 1));
            mx0 = fmaxf(mx0, __shfl_xor_sync(0xffffffffu, mx0, 2));
            mx1 = fmaxf(mx1, __shfl_xor_sync(0xffffffffu, mx1, 1));
            mx1 = fmaxf(mx1, __shfl_xor_sync(0xffffffffu, mx1, 2));
            if (tig == 0) {
                sMax[role * 128 + wm + gid]     = mx0;
                sMax[role * 128 + wm + gid + 8] = mx1;
            }
            PAIRBAR(barid);
            mx0 = fmaxf(fmaxf(mx0, sMax[(1 - role) * 128 + wm + gid]),     m0r);
            mx1 = fmaxf(fmaxf(mx1, sMax[(1 - role) * 128 + wm + gid + 8]), m1r);
            const float a0 = expf_fast(m0r - mx0);
            const float a1 = expf_fast(m1r - mx1);
            m0r = mx0; m1r = mx1;

            // ---- exp own cols + pair sum exchange ----
            float s0 = 0.f, s1 = 0.f;
            #pragma unroll
            for (int nt = 0; nt < 4; nt++) {
                float p0 = __uint_as_float(f2tf32(expf_fast(sacc[nt][0] - mx0)));
                float p1 = __uint_as_float(f2tf32(expf_fast(sacc[nt][1] - mx0)));
                float p2 = __uint_as_float(f2tf32(expf_fast(sacc[nt][2] - mx1)));
                float p3 = __uint_as_float(f2tf32(expf_fast(sacc[nt][3] - mx1)));
                s0 += p0 + p1; s1 += p2 + p3;
                sacc[nt][0] = p0; sacc[nt][1] = p1; sacc[nt][2] = p2; sacc[nt][3] = p3;
            }
            s0 += __shfl_xor_sync(0xffffffffu, s0, 1);
            s0 += __shfl_xor_sync(0xffffffffu, s0, 2);
            s1 += __shfl_xor_sync(0xffffffffu, s1, 1);
            s1 += __shfl_xor_sync(0xffffffffu, s1, 2);
            if (tig == 0) {
                sSum[role * 128 + wm + gid]     = s0;
                sSum[role * 128 + wm + gid + 8] = s1;
            }
            PAIRBAR(barid);
            s0 += sSum[(1 - role) * 128 + wm + gid];
            s1 += sSum[(1 - role) * 128 + wm + gid + 8];
            l0r = l0r * a0 + s0;
            l1r = l1r * a1 + s1;
            #pragma unroll
            for (int nt = 0; nt < 8; nt++) {
                acc[nt][0] *= a0; acc[nt][1] *= a0;
                acc[nt][2] *= a1; acc[nt][3] *= a1;
            }

            // ---- store P fragments to smem: P[pair][gid][k] pairs (r0,r1) ----
            #pragma unroll
            for (int nt = 0; nt < 4; nt++) {
                int c = kh + nt * 8 + tig * 2;
                uint32_t addr = smb + (FP_OFF + pair * 1088 + gid * 136 + 2 * c) * 4;
                STS128(addr,
                       __float_as_uint(sacc[nt][0]), __float_as_uint(sacc[nt][2]),
                       __float_as_uint(sacc[nt][1]), __float_as_uint(sacc[nt][3]));
            }
        }

        // ---- wait V[j] (exact); block sync also publishes P across pair ----
        if (more) { CPW1(); } else { CPW0(); }
        __syncthreads();

        if (active) {
            // ---- PV over own d-half, full 64 k ----
            #pragma unroll
            for (int kb = 0; kb < 8; kb++) {
                const int pidx = pair * 544 + gid * 68 + kb * 8 + tig;
                uint2 pa = P2[pidx];
                uint2 pb = P2[pidx + 4];
                uint32_t a[4] = {pa.x, pa.y, pb.x, pb.y};
                const int vrow = (kb * 4 + tig) * 132;
                #pragma unroll
                for (int nt = 0; nt < 8; nt++) {
                    uint2 vv = V2[vrow + (role * 8 + nt) * 8 + gid];
                    uint32_t bfr[2] = {vv.x, vv.y};
                    mma8(acc[nt], a, bfr);
                }
            }
        }
        __syncthreads();         // V (and P) consumed before refill

        if (more) {
            const float* vs2 = vsrc + (size_t)(k0 + 64) * 128;
            #pragma unroll
            for (int c = 0; c < 4; c++) CPA16(vdst + c * 16, vs2 + c * 4);
            CPC();
        }
    }

    // ---- epilogue: each warp writes its 16 rows x own 64-d half ----
    const float inv0 = 1.0f / l0r;
    const float inv1 = 1.0f / l1r;
    const int gr0 = q0 + wm + gid;
    const int gr1 = gr0 + 8;
    #pragma unroll
    for (int nt = 0; nt < 8; nt++) {
        int c0 = role * 64 + nt * 8 + tig * 2;
        float* o0 = g_ctx + (((size_t)b * TSEQ + gr0) * NH + h) * DH + c0;
        float* o1 = g_ctx + (((size_t)b * TSEQ + gr1) * NH + h) * DH + c0;
        *(float2*)o0 = make_float2(acc[nt][0] * inv0, acc[nt][1] * inv0);
        *(float2*)o1 = make_float2(acc[nt][2] * inv1, acc[nt][3] * inv1);
    }
}

// ---------------- launch ------------------------------------------------------
extern "C" void kernel_launch(void* const* d_in, const int* in_sizes, int n_in,
                              void* d_out, int out_size) {
    const float* x   = (const float*)d_in[0];
    const float* wq  = (const float*)d_in[1];
    const float* wk  = (const float*)d_in[2];
    const float* wv  = (const float*)d_in[3];
    const float* wo  = (const float*)d_in[4];
    const float* qnw = (const float*)d_in[5];
    const float* knw = (const float*)d_in[6];
    float* out = (float*)d_out;

    float *qkv_p, *ctx_p;
    cudaGetSymbolAddress((void**)&qkv_p, g_qkv);
    cudaGetSymbolAddress((void**)&ctx_p, g_ctx);

    build_rope_kernel<<<TSEQ, 64>>>();

    cudaFuncSetAttribute(gemm_kernel,
                         cudaFuncAttributeMaxDynamicSharedMemorySize, GEMM_SMEM);

    // merged QKV projection: N = 4096 (q 2048 | k 1024 | v 1024)
    gemm_kernel<<<dim3(32, 16), 512, GEMM_SMEM>>>(x, wq, wk, wv, 2048, 3072,
                                                  qkv_p, 4096);

    qkv_postprocess_kernel<<<16384, 256>>>(qnw, knw);

    cudaFuncSetAttribute(flash_attn_kernel,
                         cudaFuncAttributeMaxDynamicSharedMemorySize, FLASH_SMEM);
    flash_attn_kernel<<<dim3(TSEQ / 128, BQ * NH), 512, FLASH_SMEM>>>();

    // output projection
    gemm_kernel<<<dim3(16, 16), 512, GEMM_SMEM>>>(ctx_p, wo, wo, wo,
                                                  1 << 30, 1 << 30, out, DMODEL);
}

// round 15
// speedup vs baseline: 1.4824x; 1.4824x over previous
#include <cuda_runtime.h>
#include <math.h>
#include <stdint.h>

// Problem constants
#define BQ   2
#define TSEQ 2048
#define DMODEL 2048
#define NH   16
#define NKV  8
#define DH   128
#define MROWS (BQ*TSEQ)   // 4096

// ---------------- device scratch ----------------------------------------------
__device__ float g_qkv[MROWS * 4096];         // q(2048) | k(1024) | v(1024)
// g_q/g_k: [B,H,T,DH] with d-words permuted within 8-blocks: pos = 2*(d&3) + ((d>>2)&1)
__device__ float g_q  [BQ * NH  * TSEQ * DH]; // tf32 bits, pre-scaled by 1/sqrt(128)
__device__ float g_k  [BQ * NKV * TSEQ * DH]; // tf32 bits
// g_v: [B,Hkv] pair-grouped: word ((t>>3)*4 + (t&3))*256 + d*2 + ((t>>2)&1)
__device__ float g_v  [BQ * NKV * TSEQ * DH]; // tf32 bits
__device__ float g_ctx[MROWS * DMODEL];       // tf32 bits (rounded in flash epilogue)
__device__ float g_cos[TSEQ * 64];
__device__ float g_sin[TSEQ * 64];
// tf32-pre-rounded operands for the GEMMs
__device__ float g_xt  [MROWS * DMODEL];      // x rounded
__device__ float g_wt  [4096 * DMODEL];       // wq(2048) | wk(1024) | wv(1024) rounded
__device__ float g_wot [DMODEL * DMODEL];     // wo rounded

// ---------------- helpers -----------------------------------------------------
__device__ __forceinline__ uint32_t f2tf32(float f) {
    uint32_t u;
    asm("cvt.rna.tf32.f32 %0, %1;" : "=r"(u) : "f"(f));
    return u;
}
__device__ __forceinline__ uint32_t smem_u32(const void* p) {
    uint32_t a;
    asm("{ .reg .u64 t; cvta.to.shared.u64 t, %1; cvt.u32.u64 %0, t; }" : "=r"(a) : "l"(p));
    return a;
}
// D += A(m16k8 row) * B(k8n8 col), tf32
__device__ __forceinline__ void mma8(float* d, const uint32_t* a, const uint32_t* b) {
    asm volatile(
        "mma.sync.aligned.m16n8k8.row.col.f32.tf32.tf32.f32 "
        "{%0,%1,%2,%3}, {%4,%5,%6,%7}, {%8,%9}, {%0,%1,%2,%3};"
        : "+f"(d[0]), "+f"(d[1]), "+f"(d[2]), "+f"(d[3])
        : "r"(a[0]), "r"(a[1]), "r"(a[2]), "r"(a[3]), "r"(b[0]), "r"(b[1]));
}
#define CPA16(dst, src) asm volatile("cp.async.cg.shared.global [%0], [%1], 16;" :: "r"(dst), "l"(src) : "memory")
#define CPC()   asm volatile("cp.async.commit_group;" ::: "memory")
#define CPW0()  asm volatile("cp.async.wait_group 0;" ::: "memory")
#define CPW1()  asm volatile("cp.async.wait_group 1;" ::: "memory")
#define CPW2()  asm volatile("cp.async.wait_group 2;" ::: "memory")
#define PAIRBAR(id) asm volatile("bar.sync %0, 64;" :: "r"(id) : "memory")
#define STS128(addr, v0, v1, v2, v3) \
    asm volatile("st.shared.v4.b32 [%0], {%1,%2,%3,%4};" \
                 :: "r"(addr), "r"(v0), "r"(v1), "r"(v2), "r"(v3) : "memory")

// fast exp on the fma/alu pipes: x <= 0 expected
__device__ __forceinline__ float expf_fast(float x) {
    float z = x * 1.4426950408889634f;
    z = fmaxf(z, -126.0f);
    float r = z + 12582912.0f;                       // round-to-nearest integer
    int   i = __float_as_int(r) - 0x4B400000;
    float f = z - (r - 12582912.0f);                 // f in [-0.5, 0.5]
    float p = fmaf(f, 0.0013333558f, 0.0096181291f); // 2^f poly (deg 5)
    p = fmaf(f, p, 0.0555041087f);
    p = fmaf(f, p, 0.2402265069f);
    p = fmaf(f, p, 0.6931471806f);
    p = fmaf(f, p, 1.0f);
    return __int_as_float(__float_as_int(p) + (i << 23));
}

// ---------------- RoPE table --------------------------------------------------
__global__ void build_rope_kernel() {
    int t = blockIdx.x;
    int i = threadIdx.x;  // 0..63
    double inv = exp(-((double)(2 * i) / 128.0) * log(1.0e6));
    float af = (float)((double)t * inv);
    g_cos[t * 64 + i] = cosf(af);
    g_sin[t * 64 + i] = sinf(af);
}

// ---------------- tf32 pre-round copy -----------------------------------------
__global__ __launch_bounds__(256) void tf32_round_kernel(
    const float* __restrict__ src, float* __restrict__ dst, int n4)
{
    int i = blockIdx.x * 256 + threadIdx.x;
    if (i < n4) {
        float4 v = ((const float4*)src)[i];
        uint4 o;
        o.x = f2tf32(v.x); o.y = f2tf32(v.y);
        o.z = f2tf32(v.z); o.w = f2tf32(v.w);
        ((uint4*)dst)[i] = o;
    }
}

// ---------------- TF32 GEMM: C[m,n] = A[M,K] @ W[N,K]^T -----------------------
// 256x128 tile, BK=16, 4-stage cp.async, 256 threads (8 warps), warp tile 64x64.
// A and W are PRE-ROUNDED tf32 bits: no cvt in the hot loop.
#define GBM 256
#define GBN 128
#define GBK 16
#define GP  20
#define GSTG 4
#define GA_WORDS (GBM * GP)
#define GB_WORDS (GBN * GP)
#define GSTG_WORDS (GA_WORDS + GB_WORDS)
#define GEMM_SMEM (GSTG * GSTG_WORDS * 4)

__global__ __launch_bounds__(256, 1) void gemm_kernel(
    const float* __restrict__ A, const float* __restrict__ W0,
    const float* __restrict__ W1, const float* __restrict__ W2,
    int ns1, int ns2, float* __restrict__ C, int ldc)
{
    extern __shared__ float gs[];
    const int tid = threadIdx.x, lane = tid & 31, wid = tid >> 5;
    const int gid = lane >> 2, tig = lane & 3;
    const int wm = (wid & 3) * 64, wn = (wid >> 2) * 64;
    const int m0 = blockIdx.y * GBM;
    const int n0 = blockIdx.x * GBN;
    const int K = DMODEL;

    const float* Bw; int nb;
    if (n0 < ns1)      { Bw = W0; nb = n0; }
    else if (n0 < ns2) { Bw = W1; nb = n0 - ns1; }
    else               { Bw = W2; nb = n0 - ns2; }

    const float* asrc = A  + (size_t)(m0 + tid) * K;
    const float* bsrc = Bw + (size_t)(nb + (tid >> 1)) * K + (tid & 1) * 8;
    const uint32_t smb = smem_u32(gs);
    const uint32_t adst = smb + tid * GP * 4;
    const uint32_t bdst = smb + (GA_WORDS + (tid >> 1) * GP + (tid & 1) * 8) * 4;

    const int niter = K / GBK;  // 128

    #pragma unroll
    for (int s = 0; s < GSTG - 1; s++) {
        const int k0 = s * GBK;
        const uint32_t so = s * GSTG_WORDS * 4;
        #pragma unroll
        for (int c = 0; c < 4; c++) CPA16(adst + so + c * 16, asrc + k0 + c * 4);
        #pragma unroll
        for (int c = 0; c < 2; c++) CPA16(bdst + so + c * 16, bsrc + k0 + c * 4);
        CPC();
    }

    float acc[4][8][4];
    #pragma unroll
    for (int mt = 0; mt < 4; mt++)
        #pragma unroll
        for (int nt = 0; nt < 8; nt++)
            #pragma unroll
            for (int r = 0; r < 4; r++) acc[mt][nt][r] = 0.f;

    const uint32_t* gsu = (const uint32_t*)gs;

    for (int kt = 0; kt < niter; kt++) {
        if (kt + 3 <= niter) { CPW2(); }
        else if (kt + 2 == niter) { CPW1(); }
        else { CPW0(); }
        __syncthreads();

        if (kt + 3 < niter) {
            const int k0 = (kt + 3) * GBK;
            const uint32_t so = ((kt + 3) & 3) * GSTG_WORDS * 4;
            #pragma unroll
            for (int c = 0; c < 4; c++) CPA16(adst + so + c * 16, asrc + k0 + c * 4);
            #pragma unroll
            for (int c = 0; c < 2; c++) CPA16(bdst + so + c * 16, bsrc + k0 + c * 4);
            CPC();
        }

        const uint32_t* sa = gsu + (kt & 3) * GSTG_WORDS;
        const uint32_t* sb = sa + GA_WORDS;
        #pragma unroll
        for (int ks = 0; ks < 2; ks++) {
            uint32_t af[4][4], bf[8][2];
            #pragma unroll
            for (int mt = 0; mt < 4; mt++) {
                int base = (wm + mt * 16 + gid) * GP + ks * 8 + tig;
                af[mt][0] = sa[base];
                af[mt][1] = sa[base + 8 * GP];
                af[mt][2] = sa[base + 4];
                af[mt][3] = sa[base + 8 * GP + 4];
            }
            #pragma unroll
            for (int nt = 0; nt < 8; nt++) {
                int base = (wn + nt * 8 + gid) * GP + ks * 8 + tig;
                bf[nt][0] = sb[base];
                bf[nt][1] = sb[base + 4];
            }
            #pragma unroll
            for (int mt = 0; mt < 4; mt++)
                #pragma unroll
                for (int nt = 0; nt < 8; nt++)
                    mma8(acc[mt][nt], af[mt], bf[nt]);
        }
    }

    #pragma unroll
    for (int mt = 0; mt < 4; mt++) {
        #pragma unroll
        for (int nt = 0; nt < 8; nt++) {
            int r0 = m0 + wm + mt * 16 + gid;
            int c0 = n0 + wn + nt * 8 + tig * 2;
            *(float2*)&C[(size_t)r0 * ldc + c0]       = make_float2(acc[mt][nt][0], acc[mt][nt][1]);
            *(float2*)&C[(size_t)(r0 + 8) * ldc + c0] = make_float2(acc[mt][nt][2], acc[mt][nt][3]);
        }
    }
}

// ---------------- RMSNorm + RoPE (warp per head), permuted stores -------------
__global__ __launch_bounds__(256) void qkv_postprocess_kernel(
    const float* __restrict__ qnw, const float* __restrict__ knw)
{
    const int lane = threadIdx.x & 31;
    const int hidx = blockIdx.x * 8 + (threadIdx.x >> 5);
    const int tg = hidx >> 5;            // b*T + t
    const int hh = hidx & 31;
    const int b = tg / TSEQ;
    const int t = tg - b * TSEQ;

    const float* src;
    float* dst;
    const float* w = qnw;
    bool isv = false;
    float outscale = 0.08838834764831845f;
    if (hh < NH) {
        src = g_qkv + (size_t)tg * 4096 + hh * DH;
        dst = g_q + ((size_t)(b * NH + hh) * TSEQ + t) * DH;
    } else if (hh < NH + NKV) {
        int h = hh - NH;
        src = g_qkv + (size_t)tg * 4096 + 2048 + h * DH;
        w = knw;
        outscale = 1.0f;
        dst = g_k + ((size_t)(b * NKV + h) * TSEQ + t) * DH;
    } else {
        int h = hh - NH - NKV;
        src = g_qkv + (size_t)tg * 4096 + 3072 + h * DH;
        dst = g_v + (size_t)(b * NKV + h) * (TSEQ * DH)
                  + ((size_t)((t >> 3) * 4 + (t & 3))) * 256 + ((t >> 2) & 1);
        isv = true;
    }

    const int d0 = lane * 4;
    float4 x = *(const float4*)(src + d0);

    if (isv) {
        dst[(d0 + 0) * 2] = __uint_as_float(f2tf32(x.x));
        dst[(d0 + 1) * 2] = __uint_as_float(f2tf32(x.y));
        dst[(d0 + 2) * 2] = __uint_as_float(f2tf32(x.z));
        dst[(d0 + 3) * 2] = __uint_as_float(f2tf32(x.w));
        return;
    }

    float ss = x.x * x.x + x.y * x.y + x.z * x.z + x.w * x.w;
    #pragma unroll
    for (int o = 16; o > 0; o >>= 1) ss += __shfl_xor_sync(0xffffffffu, ss, o);
    const float rms = rsqrtf(ss * (1.0f / 128.0f) + 1e-6f);

    float4 wv = *(const float4*)(w + d0);
    float4 nx;
    nx.x = x.x * rms * wv.x; nx.y = x.y * rms * wv.y;
    nx.z = x.z * rms * wv.z; nx.w = x.w * rms * wv.w;

    float4 pn;
    pn.x = __shfl_xor_sync(0xffffffffu, nx.x, 16);
    pn.y = __shfl_xor_sync(0xffffffffu, nx.y, 16);
    pn.z = __shfl_xor_sync(0xffffffffu, nx.z, 16);
    pn.w = __shfl_xor_sync(0xffffffffu, nx.w, 16);
    const float sgn = (lane < 16) ? -1.0f : 1.0f;

    const int i0 = d0 & 63;
    float4 c4 = *(const float4*)(g_cos + t * 64 + i0);
    float4 s4 = *(const float4*)(g_sin + t * 64 + i0);

    float o0 = (nx.x * c4.x + sgn * pn.x * s4.x) * outscale;
    float o1 = (nx.y * c4.y + sgn * pn.y * s4.y) * outscale;
    float o2 = (nx.z * c4.z + sgn * pn.z * s4.z) * outscale;
    float o3 = (nx.w * c4.w + sgn * pn.w * s4.w) * outscale;

    float* pd = dst + (lane >> 1) * 8 + (lane & 1);
    pd[0] = __uint_as_float(f2tf32(o0));
    pd[2] = __uint_as_float(f2tf32(o1));
    pd[4] = __uint_as_float(f2tf32(o2));
    pd[6] = __uint_as_float(f2tf32(o3));
}

// ---------------- Flash attention v6: 128q tile, d-split pairs, P via smem ----
#define FQ_OFF  0
#define FK_OFF  17408                 // Q: 128*136
#define FV_OFF  (FK_OFF + 8704)      // K: 64*136
#define FP_OFF  (FV_OFF + 8448)      // V: 32*264
#define FEX_OFF (FP_OFF + 8704)      // P: 8 pairs * 8 * 136
#define FLASH_WORDS (FEX_OFF + 512)
#define FLASH_SMEM (FLASH_WORDS * 4) // 175104 B

__global__ __launch_bounds__(512, 1) void flash_attn_kernel() {
    extern __shared__ float fsm[];
    const uint2* Q2 = (const uint2*)fsm;                 // pitch 68 uint2
    const uint2* K2 = (const uint2*)(fsm + FK_OFF);
    const uint2* V2 = (const uint2*)(fsm + FV_OFF);
    const uint2* P2 = (const uint2*)(fsm + FP_OFF);
    float* sMax = fsm + FEX_OFF;        // [2][128]
    float* sSum = fsm + FEX_OFF + 256;  // [2][128]

    const int tid  = threadIdx.x;
    const int lane = tid & 31;
    const int wid  = tid >> 5;           // 0..15
    const int gid  = lane >> 2;
    const int tig  = lane & 3;
    const int pair = wid & 7;
    const int role = wid >> 3;           // 0/1: k-half in S, d-half in PV
    const int wm   = pair * 16;
    const int kh   = role * 32;
    const int barid = pair + 1;

    const int bh = blockIdx.y;
    const int b = bh >> 4;
    const int h = bh & 15;
    const int hk = h >> 1;
    const int q0 = (15 - (int)blockIdx.x) * 128;   // big blocks first
    const int ntiles = (q0 >> 6) + 2;

    const float* Qg = g_q + ((size_t)(b * NH + h) * TSEQ + q0) * DH;
    const float* Kg = g_k + (size_t)(b * NKV + hk) * TSEQ * DH;
    const float* Vg = g_v + (size_t)(b * NKV + hk) * (TSEQ * DH);

    // cp.async loader geometry (512 threads)
    const uint32_t smb = smem_u32(fsm);
    const int qr = tid >> 2, qs = (tid & 3) * 32;        // Q: 128 rows
    const uint32_t qdst = smb + (qr * 136 + qs) * 4;
    const float* qsrc = Qg + (size_t)qr * DH + qs;
    const int kr = tid >> 3, ksg = (tid & 7) * 16;       // K: 64 rows
    const uint32_t kdst = smb + (FK_OFF + kr * 136 + ksg) * 4;
    const float* ksrc = Kg + (size_t)kr * DH + ksg;
    const int vgr = tid >> 4, vsg = (tid & 15) * 16;     // V: 32 groups
    const uint32_t vdst = smb + (FV_OFF + vgr * 264 + vsg) * 4;
    const float* vsrc = Vg + vgr * 256 + vsg;

    // prologue: {Q + K[0]} group, {V[0]} group
    #pragma unroll
    for (int c = 0; c < 8; c++) CPA16(qdst + c * 16, qsrc + c * 4);
    #pragma unroll
    for (int c = 0; c < 4; c++) CPA16(kdst + c * 16, ksrc + c * 4);
    CPC();
    #pragma unroll
    for (int c = 0; c < 4; c++) CPA16(vdst + c * 16, vsrc + c * 4);
    CPC();

    float acc[8][4];                      // PV for own d-half (full k)
    #pragma unroll
    for (int nt = 0; nt < 8; nt++)
        #pragma unroll
        for (int r = 0; r < 4; r++) acc[nt][r] = 0.f;
    float m0r = -INFINITY, m1r = -INFINITY, l0r = 0.f, l1r = 0.f;

    const int pr0 = wm + gid, pr1 = pr0 + 8;   // pair-local q rows (block view)

    for (int j = 0; j < ntiles; j++) {
        const int k0 = j * 64;
        const bool more = (j + 1 < ntiles);
        const bool active = (q0 + wm + 15) >= k0;

        CPW1();                  // K[j] (+Q) resident; V[j] may be pending
        __syncthreads();

        // ---- S = Q @ K^T over own k-half (16 x 32) ----
        float sacc[4][4];
        #pragma unroll
        for (int nt = 0; nt < 4; nt++)
            #pragma unroll
            for (int r = 0; r < 4; r++) sacc[nt][r] = 0.f;

        if (active) {
            #pragma unroll
            for (int ks = 0; ks < 16; ks++) {
                uint32_t af[4];
                const int qo = ((wm + gid) * 136 + ks * 8 + tig * 2) >> 1;
                uint2 qa = Q2[qo];
                uint2 qb = Q2[qo + 8 * 68];
                af[0] = qa.x; af[2] = qa.y;
                af[1] = qb.x; af[3] = qb.y;
                #pragma unroll
                for (int nt = 0; nt < 4; nt++) {
                    uint2 kb2 = K2[((kh + nt * 8 + gid) * 136 + ks * 8 + tig * 2) >> 1];
                    uint32_t bfr[2] = {kb2.x, kb2.y};
                    mma8(sacc[nt], af, bfr);
                }
            }
        }
        __syncthreads();         // K consumed by all

        if (more) {
            const float* ks2 = ksrc + (size_t)(k0 + 64) * DH;
            #pragma unroll
            for (int c = 0; c < 4; c++) CPA16(kdst + c * 16, ks2 + c * 4);
            CPC();
        }

        if (active) {
            // ---- mask near-diagonal tiles ----
            const int off = q0 - k0;    // mask if local col c0 > off + row
            if (off < 64) {
                #pragma unroll
                for (int nt = 0; nt < 4; nt++) {
                    int c0 = kh + nt * 8 + tig * 2;
                    if (c0     > off + pr0) sacc[nt][0] = -1e30f;
                    if (c0 + 1 > off + pr0) sacc[nt][1] = -1e30f;
                    if (c0     > off + pr1) sacc[nt][2] = -1e30f;
                    if (c0 + 1 > off + pr1) sacc[nt][3] = -1e30f;
                }
            }

            // ---- partial max + pair exchange ----
            float mx0 = -INFINITY, mx1 = -INFINITY;
            #pragma unroll
            for (int nt = 0; nt < 4; nt++) {
                mx0 = fmaxf(mx0, fmaxf(sacc[nt][0], sacc[nt][1]));
                mx1 = fmaxf(mx1, fmaxf(sacc[nt][2], sacc[nt][3]));
            }
            mx0 = fmaxf(mx0, __shfl_xor_sync(0xffffffffu, mx0, 1));
            mx0 = fmaxf(mx0, __shfl_xor_sync(0xffffffffu, mx0, 2));
            mx1 = fmaxf(mx1, __shfl_xor_sync(0xffffffffu, mx1, 1));
            mx1 = fmaxf(mx1, __shfl_xor_sync(0xffffffffu, mx1, 2));
            if (tig == 0) {
                sMax[role * 128 + wm + gid]     = mx0;
                sMax[role * 128 + wm + gid + 8] = mx1;
            }
            PAIRBAR(barid);
            mx0 = fmaxf(fmaxf(mx0, sMax[(1 - role) * 128 + wm + gid]),     m0r);
            mx1 = fmaxf(fmaxf(mx1, sMax[(1 - role) * 128 + wm + gid + 8]), m1r);
            const float a0 = expf_fast(m0r - mx0);
            const float a1 = expf_fast(m1r - mx1);
            m0r = mx0; m1r = mx1;

            // ---- exp own cols + pair sum exchange ----
            float s0 = 0.f, s1 = 0.f;
            #pragma unroll
            for (int nt = 0; nt < 4; nt++) {
                float p0 = __uint_as_float(f2tf32(expf_fast(sacc[nt][0] - mx0)));
                float p1 = __uint_as_float(f2tf32(expf_fast(sacc[nt][1] - mx0)));
                float p2 = __uint_as_float(f2tf32(expf_fast(sacc[nt][2] - mx1)));
                float p3 = __uint_as_float(f2tf32(expf_fast(sacc[nt][3] - mx1)));
                s0 += p0 + p1; s1 += p2 + p3;
                sacc[nt][0] = p0; sacc[nt][1] = p1; sacc[nt][2] = p2; sacc[nt][3] = p3;
            }
            s0 += __shfl_xor_sync(0xffffffffu, s0, 1);
            s0 += __shfl_xor_sync(0xffffffffu, s0, 2);
            s1 += __shfl_xor_sync(0xffffffffu, s1, 1);
            s1 += __shfl_xor_sync(0xffffffffu, s1, 2);
            if (tig == 0) {
                sSum[role * 128 + wm + gid]     = s0;
                sSum[role * 128 + wm + gid + 8] = s1;
            }
            PAIRBAR(barid);
            s0 += sSum[(1 - role) * 128 + wm + gid];
            s1 += sSum[(1 - role) * 128 + wm + gid + 8];
            l0r = l0r * a0 + s0;
            l1r = l1r * a1 + s1;
            #pragma unroll
            for (int nt = 0; nt < 8; nt++) {
                acc[nt][0] *= a0; acc[nt][1] *= a0;
                acc[nt][2] *= a1; acc[nt][3] *= a1;
            }

            // ---- store P fragments to smem: P[pair][gid][k] pairs (r0,r1) ----
            #pragma unroll
            for (int nt = 0; nt < 4; nt++) {
                int c = kh + nt * 8 + tig * 2;
                uint32_t addr = smb + (FP_OFF + pair * 1088 + gid * 136 + 2 * c) * 4;
                STS128(addr,
                       __float_as_uint(sacc[nt][0]), __float_as_uint(sacc[nt][2]),
                       __float_as_uint(sacc[nt][1]), __float_as_uint(sacc[nt][3]));
            }
        }

        // ---- wait V[j] (exact); block sync also publishes P across pair ----
        if (more) { CPW1(); } else { CPW0(); }
        __syncthreads();

        if (active) {
            // ---- PV over own d-half, full 64 k ----
            #pragma unroll
            for (int kb = 0; kb < 8; kb++) {
                const int pidx = pair * 544 + gid * 68 + kb * 8 + tig;
                uint2 pa = P2[pidx];
                uint2 pb = P2[pidx + 4];
                uint32_t a[4] = {pa.x, pa.y, pb.x, pb.y};
                const int vrow = (kb * 4 + tig) * 132;
                #pragma unroll
                for (int nt = 0; nt < 8; nt++) {
                    uint2 vv = V2[vrow + (role * 8 + nt) * 8 + gid];
                    uint32_t bfr[2] = {vv.x, vv.y};
                    mma8(acc[nt], a, bfr);
                }
            }
        }
        __syncthreads();         // V (and P) consumed before refill

        if (more) {
            const float* vs2 = vsrc + (size_t)(k0 + 64) * 128;
            #pragma unroll
            for (int c = 0; c < 4; c++) CPA16(vdst + c * 16, vs2 + c * 4);
            CPC();
        }
    }

    // ---- epilogue: each warp writes its 16 rows x own 64-d half, tf32-rounded
    const float inv0 = 1.0f / l0r;
    const float inv1 = 1.0f / l1r;
    const int gr0 = q0 + wm + gid;
    const int gr1 = gr0 + 8;
    #pragma unroll
    for (int nt = 0; nt < 8; nt++) {
        int c0 = role * 64 + nt * 8 + tig * 2;
        float* o0 = g_ctx + (((size_t)b * TSEQ + gr0) * NH + h) * DH + c0;
        float* o1 = g_ctx + (((size_t)b * TSEQ + gr1) * NH + h) * DH + c0;
        *(float2*)o0 = make_float2(__uint_as_float(f2tf32(acc[nt][0] * inv0)),
                                   __uint_as_float(f2tf32(acc[nt][1] * inv0)));
        *(float2*)o1 = make_float2(__uint_as_float(f2tf32(acc[nt][2] * inv1)),
                                   __uint_as_float(f2tf32(acc[nt][3] * inv1)));
    }
}

// ---------------- launch ------------------------------------------------------
extern "C" void kernel_launch(void* const* d_in, const int* in_sizes, int n_in,
                              void* d_out, int out_size) {
    const float* x   = (const float*)d_in[0];
    const float* wq  = (const float*)d_in[1];
    const float* wk  = (const float*)d_in[2];
    const float* wv  = (const float*)d_in[3];
    const float* wo  = (const float*)d_in[4];
    const float* qnw = (const float*)d_in[5];
    const float* knw = (const float*)d_in[6];
    float* out = (float*)d_out;

    float *qkv_p, *ctx_p, *xt_p, *wt_p, *wot_p;
    cudaGetSymbolAddress((void**)&qkv_p, g_qkv);
    cudaGetSymbolAddress((void**)&ctx_p, g_ctx);
    cudaGetSymbolAddress((void**)&xt_p, g_xt);
    cudaGetSymbolAddress((void**)&wt_p, g_wt);
    cudaGetSymbolAddress((void**)&wot_p, g_wot);

    build_rope_kernel<<<TSEQ, 64>>>();

    // pre-round operands to tf32 (removes cvt from GEMM hot loops)
    tf32_round_kernel<<<8192, 256>>>(x,  xt_p,  MROWS * DMODEL / 4);
    tf32_round_kernel<<<4096, 256>>>(wq, wt_p,                2048 * DMODEL / 4);
    tf32_round_kernel<<<2048, 256>>>(wk, wt_p + 2048 * DMODEL, 1024 * DMODEL / 4);
    tf32_round_kernel<<<2048, 256>>>(wv, wt_p + 3072 * DMODEL, 1024 * DMODEL / 4);
    tf32_round_kernel<<<4096, 256>>>(wo, wot_p,               DMODEL * DMODEL / 4);

    cudaFuncSetAttribute(gemm_kernel,
                         cudaFuncAttributeMaxDynamicSharedMemorySize, GEMM_SMEM);

    // merged QKV projection: N = 4096 (q 2048 | k 1024 | v 1024)
    gemm_kernel<<<dim3(32, 16), 256, GEMM_SMEM>>>(xt_p, wt_p,
                                                  wt_p + 2048 * DMODEL,
                                                  wt_p + 3072 * DMODEL,
                                                  2048, 3072, qkv_p, 4096);

    qkv_postprocess_kernel<<<16384, 256>>>(qnw, knw);

    cudaFuncSetAttribute(flash_attn_kernel,
                         cudaFuncAttributeMaxDynamicSharedMemorySize, FLASH_SMEM);
    flash_attn_kernel<<<dim3(TSEQ / 128, BQ * NH), 512, FLASH_SMEM>>>();

    // output projection (ctx already tf32-rounded by flash epilogue)
    gemm_kernel<<<dim3(16, 16), 256, GEMM_SMEM>>>(ctx_p, wot_p, wot_p, wot_p,
                                                  1 << 30, 1 << 30, out, DMODEL);
}

// round 16
// speedup vs baseline: 1.6000x; 1.0793x over previous
#include <cuda_runtime.h>
#include <math.h>
#include <stdint.h>

// Problem constants
#define BQ   2
#define TSEQ 2048
#define DMODEL 2048
#define NH   16
#define NKV  8
#define DH   128
#define MROWS (BQ*TSEQ)   // 4096

// ---------------- device scratch ----------------------------------------------
__device__ float g_qkv[MROWS * 4096];         // q(2048) | k(1024) | v(1024)
// g_q/g_k: [B,H,T,DH] with d-words permuted within 8-blocks: pos = 2*(d&3) + ((d>>2)&1)
__device__ float g_q  [BQ * NH  * TSEQ * DH]; // tf32 bits, pre-scaled by 1/sqrt(128)
__device__ float g_k  [BQ * NKV * TSEQ * DH]; // tf32 bits
// g_v: [B,Hkv] pair-grouped: word ((t>>3)*4 + (t&3))*256 + d*2 + ((t>>2)&1)
__device__ float g_v  [BQ * NKV * TSEQ * DH]; // tf32 bits
__device__ float g_ctx[MROWS * DMODEL];       // tf32 bits (rounded in flash epilogue)
__device__ float g_cos[TSEQ * 64];
__device__ float g_sin[TSEQ * 64];
// tf32-pre-rounded operands for the GEMMs
__device__ float g_xt  [MROWS * DMODEL];      // x rounded
__device__ float g_wt  [4096 * DMODEL];       // wq(2048) | wk(1024) | wv(1024) rounded
__device__ float g_wot [DMODEL * DMODEL];     // wo rounded

// ---------------- helpers -----------------------------------------------------
__device__ __forceinline__ uint32_t f2tf32(float f) {
    uint32_t u;
    asm("cvt.rna.tf32.f32 %0, %1;" : "=r"(u) : "f"(f));
    return u;
}
__device__ __forceinline__ uint32_t smem_u32(const void* p) {
    uint32_t a;
    asm("{ .reg .u64 t; cvta.to.shared.u64 t, %1; cvt.u32.u64 %0, t; }" : "=r"(a) : "l"(p));
    return a;
}
// D += A(m16k8 row) * B(k8n8 col), tf32
__device__ __forceinline__ void mma8(float* d, const uint32_t* a, const uint32_t* b) {
    asm volatile(
        "mma.sync.aligned.m16n8k8.row.col.f32.tf32.tf32.f32 "
        "{%0,%1,%2,%3}, {%4,%5,%6,%7}, {%8,%9}, {%0,%1,%2,%3};"
        : "+f"(d[0]), "+f"(d[1]), "+f"(d[2]), "+f"(d[3])
        : "r"(a[0]), "r"(a[1]), "r"(a[2]), "r"(a[3]), "r"(b[0]), "r"(b[1]));
}
#define CPA16(dst, src) asm volatile("cp.async.cg.shared.global [%0], [%1], 16;" :: "r"(dst), "l"(src) : "memory")
#define CPC()   asm volatile("cp.async.commit_group;" ::: "memory")
#define CPW0()  asm volatile("cp.async.wait_group 0;" ::: "memory")
#define CPW1()  asm volatile("cp.async.wait_group 1;" ::: "memory")
#define CPW2()  asm volatile("cp.async.wait_group 2;" ::: "memory")
#define PAIRBAR(id) asm volatile("bar.sync %0, 64;" :: "r"(id) : "memory")
#define STS128(addr, v0, v1, v2, v3) \
    asm volatile("st.shared.v4.b32 [%0], {%1,%2,%3,%4};" \
                 :: "r"(addr), "r"(v0), "r"(v1), "r"(v2), "r"(v3) : "memory")

// fast exp on the fma/alu pipes: x <= 0 expected
__device__ __forceinline__ float expf_fast(float x) {
    float z = x * 1.4426950408889634f;
    z = fmaxf(z, -126.0f);
    float r = z + 12582912.0f;                       // round-to-nearest integer
    int   i = __float_as_int(r) - 0x4B400000;
    float f = z - (r - 12582912.0f);                 // f in [-0.5, 0.5]
    float p = fmaf(f, 0.0013333558f, 0.0096181291f); // 2^f poly (deg 5)
    p = fmaf(f, p, 0.0555041087f);
    p = fmaf(f, p, 0.2402265069f);
    p = fmaf(f, p, 0.6931471806f);
    p = fmaf(f, p, 1.0f);
    return __int_as_float(__float_as_int(p) + (i << 23));
}

// ---------------- RoPE table --------------------------------------------------
__global__ void build_rope_kernel() {
    int t = blockIdx.x;
    int i = threadIdx.x;  // 0..63
    double inv = exp(-((double)(2 * i) / 128.0) * log(1.0e6));
    float af = (float)((double)t * inv);
    g_cos[t * 64 + i] = cosf(af);
    g_sin[t * 64 + i] = sinf(af);
}

// ---------------- tf32 pre-round copy -----------------------------------------
__global__ __launch_bounds__(256) void tf32_round_kernel(
    const float* __restrict__ src, float* __restrict__ dst, int n4)
{
    int i = blockIdx.x * 256 + threadIdx.x;
    if (i < n4) {
        float4 v = ((const float4*)src)[i];
        uint4 o;
        o.x = f2tf32(v.x); o.y = f2tf32(v.y);
        o.z = f2tf32(v.z); o.w = f2tf32(v.w);
        ((uint4*)dst)[i] = o;
    }
}

// ---------------- TF32 GEMM: C[m,n] = A[M,K] @ W[N,K]^T -----------------------
// 256x128 tile, BK=16, 4-stage cp.async, 512 threads (16 warps), warp tile 64x32.
// Operands PRE-ROUNDED tf32 bits: no cvt in the hot loop.
#define GBM 256
#define GBN 128
#define GBK 16
#define GP  20
#define GSTG 4
#define GA_WORDS (GBM * GP)
#define GB_WORDS (GBN * GP)
#define GSTG_WORDS (GA_WORDS + GB_WORDS)
#define GEMM_SMEM (GSTG * GSTG_WORDS * 4)

__global__ __launch_bounds__(512, 1) void gemm_kernel(
    const float* __restrict__ A, const float* __restrict__ W0,
    const float* __restrict__ W1, const float* __restrict__ W2,
    int ns1, int ns2, float* __restrict__ C, int ldc)
{
    extern __shared__ float gs[];
    const int tid = threadIdx.x, lane = tid & 31, wid = tid >> 5;
    const int gid = lane >> 2, tig = lane & 3;
    const int wm = (wid & 3) * 64, wn = (wid >> 2) * 32;
    const int m0 = blockIdx.y * GBM;
    const int n0 = blockIdx.x * GBN;
    const int K = DMODEL;

    const float* Bw; int nb;
    if (n0 < ns1)      { Bw = W0; nb = n0; }
    else if (n0 < ns2) { Bw = W1; nb = n0 - ns1; }
    else               { Bw = W2; nb = n0 - ns2; }

    // loaders: A row tid>>1, half (tid&1)*8 (2 chunks); B row tid>>2, (tid&3)*4 (1 chunk)
    const int arow = tid >> 1, akseg = (tid & 1) * 8;
    const int brow = tid >> 2, bkseg = (tid & 3) * 4;
    const float* asrc = A  + (size_t)(m0 + arow) * K + akseg;
    const float* bsrc = Bw + (size_t)(nb + brow) * K + bkseg;
    const uint32_t smb = smem_u32(gs);
    const uint32_t adst = smb + (arow * GP + akseg) * 4;
    const uint32_t bdst = smb + (GA_WORDS + brow * GP + bkseg) * 4;

    const int niter = K / GBK;  // 128

    #pragma unroll
    for (int s = 0; s < GSTG - 1; s++) {
        const int k0 = s * GBK;
        const uint32_t so = s * GSTG_WORDS * 4;
        CPA16(adst + so,      asrc + k0);
        CPA16(adst + so + 16, asrc + k0 + 4);
        CPA16(bdst + so,      bsrc + k0);
        CPC();
    }

    float acc[4][4][4];
    #pragma unroll
    for (int mt = 0; mt < 4; mt++)
        #pragma unroll
        for (int nt = 0; nt < 4; nt++)
            #pragma unroll
            for (int r = 0; r < 4; r++) acc[mt][nt][r] = 0.f;

    const uint32_t* gsu = (const uint32_t*)gs;

    for (int kt = 0; kt < niter; kt++) {
        if (kt + 3 <= niter) { CPW2(); }
        else if (kt + 2 == niter) { CPW1(); }
        else { CPW0(); }
        __syncthreads();

        if (kt + 3 < niter) {
            const int k0 = (kt + 3) * GBK;
            const uint32_t so = ((kt + 3) & 3) * GSTG_WORDS * 4;
            CPA16(adst + so,      asrc + k0);
            CPA16(adst + so + 16, asrc + k0 + 4);
            CPA16(bdst + so,      bsrc + k0);
            CPC();
        }

        const uint32_t* sa = gsu + (kt & 3) * GSTG_WORDS;
        const uint32_t* sb = sa + GA_WORDS;
        #pragma unroll
        for (int ks = 0; ks < 2; ks++) {
            uint32_t af[4][4], bf[4][2];
            #pragma unroll
            for (int mt = 0; mt < 4; mt++) {
                int base = (wm + mt * 16 + gid) * GP + ks * 8 + tig;
                af[mt][0] = sa[base];
                af[mt][1] = sa[base + 8 * GP];
                af[mt][2] = sa[base + 4];
                af[mt][3] = sa[base + 8 * GP + 4];
            }
            #pragma unroll
            for (int nt = 0; nt < 4; nt++) {
                int base = (wn + nt * 8 + gid) * GP + ks * 8 + tig;
                bf[nt][0] = sb[base];
                bf[nt][1] = sb[base + 4];
            }
            #pragma unroll
            for (int mt = 0; mt < 4; mt++)
                #pragma unroll
                for (int nt = 0; nt < 4; nt++)
                    mma8(acc[mt][nt], af[mt], bf[nt]);
        }
    }

    #pragma unroll
    for (int mt = 0; mt < 4; mt++) {
        #pragma unroll
        for (int nt = 0; nt < 4; nt++) {
            int r0 = m0 + wm + mt * 16 + gid;
            int c0 = n0 + wn + nt * 8 + tig * 2;
            *(float2*)&C[(size_t)r0 * ldc + c0]       = make_float2(acc[mt][nt][0], acc[mt][nt][1]);
            *(float2*)&C[(size_t)(r0 + 8) * ldc + c0] = make_float2(acc[mt][nt][2], acc[mt][nt][3]);
        }
    }
}

// ---------------- RMSNorm + RoPE (warp per head), permuted stores -------------
__global__ __launch_bounds__(256) void qkv_postprocess_kernel(
    const float* __restrict__ qnw, const float* __restrict__ knw)
{
    const int lane = threadIdx.x & 31;
    const int hidx = blockIdx.x * 8 + (threadIdx.x >> 5);
    const int tg = hidx >> 5;            // b*T + t
    const int hh = hidx & 31;
    const int b = tg / TSEQ;
    const int t = tg - b * TSEQ;

    const float* src;
    float* dst;
    const float* w = qnw;
    bool isv = false;
    float outscale = 0.08838834764831845f;
    if (hh < NH) {
        src = g_qkv + (size_t)tg * 4096 + hh * DH;
        dst = g_q + ((size_t)(b * NH + hh) * TSEQ + t) * DH;
    } else if (hh < NH + NKV) {
        int h = hh - NH;
        src = g_qkv + (size_t)tg * 4096 + 2048 + h * DH;
        w = knw;
        outscale = 1.0f;
        dst = g_k + ((size_t)(b * NKV + h) * TSEQ + t) * DH;
    } else {
        int h = hh - NH - NKV;
        src = g_qkv + (size_t)tg * 4096 + 3072 + h * DH;
        dst = g_v + (size_t)(b * NKV + h) * (TSEQ * DH)
                  + ((size_t)((t >> 3) * 4 + (t & 3))) * 256 + ((t >> 2) & 1);
        isv = true;
    }

    const int d0 = lane * 4;
    float4 x = *(const float4*)(src + d0);

    if (isv) {
        dst[(d0 + 0) * 2] = __uint_as_float(f2tf32(x.x));
        dst[(d0 + 1) * 2] = __uint_as_float(f2tf32(x.y));
        dst[(d0 + 2) * 2] = __uint_as_float(f2tf32(x.z));
        dst[(d0 + 3) * 2] = __uint_as_float(f2tf32(x.w));
        return;
    }

    float ss = x.x * x.x + x.y * x.y + x.z * x.z + x.w * x.w;
    #pragma unroll
    for (int o = 16; o > 0; o >>= 1) ss += __shfl_xor_sync(0xffffffffu, ss, o);
    const float rms = rsqrtf(ss * (1.0f / 128.0f) + 1e-6f);

    float4 wv = *(const float4*)(w + d0);
    float4 nx;
    nx.x = x.x * rms * wv.x; nx.y = x.y * rms * wv.y;
    nx.z = x.z * rms * wv.z; nx.w = x.w * rms * wv.w;

    float4 pn;
    pn.x = __shfl_xor_sync(0xffffffffu, nx.x, 16);
    pn.y = __shfl_xor_sync(0xffffffffu, nx.y, 16);
    pn.z = __shfl_xor_sync(0xffffffffu, nx.z, 16);
    pn.w = __shfl_xor_sync(0xffffffffu, nx.w, 16);
    const float sgn = (lane < 16) ? -1.0f : 1.0f;

    const int i0 = d0 & 63;
    float4 c4 = *(const float4*)(g_cos + t * 64 + i0);
    float4 s4 = *(const float4*)(g_sin + t * 64 + i0);

    float o0 = (nx.x * c4.x + sgn * pn.x * s4.x) * outscale;
    float o1 = (nx.y * c4.y + sgn * pn.y * s4.y) * outscale;
    float o2 = (nx.z * c4.z + sgn * pn.z * s4.z) * outscale;
    float o3 = (nx.w * c4.w + sgn * pn.w * s4.w) * outscale;

    float* pd = dst + (lane >> 1) * 8 + (lane & 1);
    pd[0] = __uint_as_float(f2tf32(o0));
    pd[2] = __uint_as_float(f2tf32(o1));
    pd[4] = __uint_as_float(f2tf32(o2));
    pd[6] = __uint_as_float(f2tf32(o3));
}

// ---------------- Flash attention v6: 128q tile, d-split pairs, P via smem ----
#define FQ_OFF  0
#define FK_OFF  17408                 // Q: 128*136
#define FV_OFF  (FK_OFF + 8704)      // K: 64*136
#define FP_OFF  (FV_OFF + 8448)      // V: 32*264
#define FEX_OFF (FP_OFF + 8704)      // P: 8 pairs * 8 * 136
#define FLASH_WORDS (FEX_OFF + 512)
#define FLASH_SMEM (FLASH_WORDS * 4) // 175104 B

__global__ __launch_bounds__(512, 1) void flash_attn_kernel() {
    extern __shared__ float fsm[];
    const uint2* Q2 = (const uint2*)fsm;                 // pitch 68 uint2
    const uint2* K2 = (const uint2*)(fsm + FK_OFF);
    const uint2* V2 = (const uint2*)(fsm + FV_OFF);
    const uint2* P2 = (const uint2*)(fsm + FP_OFF);
    float* sMax = fsm + FEX_OFF;        // [2][128]
    float* sSum = fsm + FEX_OFF + 256;  // [2][128]

    const int tid  = threadIdx.x;
    const int lane = tid & 31;
    const int wid  = tid >> 5;           // 0..15
    const int gid  = lane >> 2;
    const int tig  = lane & 3;
    const int pair = wid & 7;
    const int role = wid >> 3;           // 0/1: k-half in S, d-half in PV
    const int wm   = pair * 16;
    const int kh   = role * 32;
    const int barid = pair + 1;

    const int bh = blockIdx.y;
    const int b = bh >> 4;
    const int h = bh & 15;
    const int hk = h >> 1;
    const int q0 = (15 - (int)blockIdx.x) * 128;   // big blocks first
    const int ntiles = (q0 >> 6) + 2;

    const float* Qg = g_q + ((size_t)(b * NH + h) * TSEQ + q0) * DH;
    const float* Kg = g_k + (size_t)(b * NKV + hk) * TSEQ * DH;
    const float* Vg = g_v + (size_t)(b * NKV + hk) * (TSEQ * DH);

    // cp.async loader geometry (512 threads)
    const uint32_t smb = smem_u32(fsm);
    const int qr = tid >> 2, qs = (tid & 3) * 32;        // Q: 128 rows
    const uint32_t qdst = smb + (qr * 136 + qs) * 4;
    const float* qsrc = Qg + (size_t)qr * DH + qs;
    const int kr = tid >> 3, ksg = (tid & 7) * 16;       // K: 64 rows
    const uint32_t kdst = smb + (FK_OFF + kr * 136 + ksg) * 4;
    const float* ksrc = Kg + (size_t)kr * DH + ksg;
    const int vgr = tid >> 4, vsg = (tid & 15) * 16;     // V: 32 groups
    const uint32_t vdst = smb + (FV_OFF + vgr * 264 + vsg) * 4;
    const float* vsrc = Vg + vgr * 256 + vsg;

    // prologue: {Q + K[0]} group, {V[0]} group
    #pragma unroll
    for (int c = 0; c < 8; c++) CPA16(qdst + c * 16, qsrc + c * 4);
    #pragma unroll
    for (int c = 0; c < 4; c++) CPA16(kdst + c * 16, ksrc + c * 4);
    CPC();
    #pragma unroll
    for (int c = 0; c < 4; c++) CPA16(vdst + c * 16, vsrc + c * 4);
    CPC();

    float acc[8][4];                      // PV for own d-half (full k)
    #pragma unroll
    for (int nt = 0; nt < 8; nt++)
        #pragma unroll
        for (int r = 0; r < 4; r++) acc[nt][r] = 0.f;
    float m0r = -INFINITY, m1r = -INFINITY, l0r = 0.f, l1r = 0.f;

    const int pr0 = wm + gid, pr1 = pr0 + 8;   // pair-local q rows (block view)

    for (int j = 0; j < ntiles; j++) {
        const int k0 = j * 64;
        const bool more = (j + 1 < ntiles);
        const bool active = (q0 + wm + 15) >= k0;

        CPW1();                  // K[j] (+Q) resident; V[j] may be pending
        __syncthreads();

        // ---- S = Q @ K^T over own k-half (16 x 32) ----
        float sacc[4][4];
        #pragma unroll
        for (int nt = 0; nt < 4; nt++)
            #pragma unroll
            for (int r = 0; r < 4; r++) sacc[nt][r] = 0.f;

        if (active) {
            #pragma unroll
            for (int ks = 0; ks < 16; ks++) {
                uint32_t af[4];
                const int qo = ((wm + gid) * 136 + ks * 8 + tig * 2) >> 1;
                uint2 qa = Q2[qo];
                uint2 qb = Q2[qo + 8 * 68];
                af[0] = qa.x; af[2] = qa.y;
                af[1] = qb.x; af[3] = qb.y;
                #pragma unroll
                for (int nt = 0; nt < 4; nt++) {
                    uint2 kb2 = K2[((kh + nt * 8 + gid) * 136 + ks * 8 + tig * 2) >> 1];
                    uint32_t bfr[2] = {kb2.x, kb2.y};
                    mma8(sacc[nt], af, bfr);
                }
            }
        }
        __syncthreads();         // K consumed by all

        if (more) {
            const float* ks2 = ksrc + (size_t)(k0 + 64) * DH;
            #pragma unroll
            for (int c = 0; c < 4; c++) CPA16(kdst + c * 16, ks2 + c * 4);
            CPC();
        }

        if (active) {
            // ---- mask near-diagonal tiles ----
            const int off = q0 - k0;    // mask if local col c0 > off + row
            if (off < 64) {
                #pragma unroll
                for (int nt = 0; nt < 4; nt++) {
                    int c0 = kh + nt * 8 + tig * 2;
                    if (c0     > off + pr0) sacc[nt][0] = -1e30f;
                    if (c0 + 1 > off + pr0) sacc[nt][1] = -1e30f;
                    if (c0     > off + pr1) sacc[nt][2] = -1e30f;
                    if (c0 + 1 > off + pr1) sacc[nt][3] = -1e30f;
                }
            }

            // ---- partial max + pair exchange ----
            float mx0 = -INFINITY, mx1 = -INFINITY;
            #pragma unroll
            for (int nt = 0; nt < 4; nt++) {
                mx0 = fmaxf(mx0, fmaxf(sacc[nt][0], sacc[nt][1]));
                mx1 = fmaxf(mx1, fmaxf(sacc[nt][2], sacc[nt][3]));
            }
            mx0 = fmaxf(mx0, __shfl_xor_sync(0xffffffffu, mx0, 1));
            mx0 = fmaxf(mx0, __shfl_xor_sync(0xffffffffu, mx0, 2));
            mx1 = fmaxf(mx1, __shfl_xor_sync(0xffffffffu, mx1, 1));
            mx1 = fmaxf(mx1, __shfl_xor_sync(0xffffffffu, mx1, 2));
            if (tig == 0) {
                sMax[role * 128 + wm + gid]     = mx0;
                sMax[role * 128 + wm + gid + 8] = mx1;
            }
            PAIRBAR(barid);
            mx0 = fmaxf(fmaxf(mx0, sMax[(1 - role) * 128 + wm + gid]),     m0r);
            mx1 = fmaxf(fmaxf(mx1, sMax[(1 - role) * 128 + wm + gid + 8]), m1r);
            const float a0 = expf_fast(m0r - mx0);
            const float a1 = expf_fast(m1r - mx1);
            m0r = mx0; m1r = mx1;

            // ---- exp own cols + pair sum exchange ----
            float s0 = 0.f, s1 = 0.f;
            #pragma unroll
            for (int nt = 0; nt < 4; nt++) {
                float p0 = __uint_as_float(f2tf32(expf_fast(sacc[nt][0] - mx0)));
                float p1 = __uint_as_float(f2tf32(expf_fast(sacc[nt][1] - mx0)));
                float p2 = __uint_as_float(f2tf32(expf_fast(sacc[nt][2] - mx1)));
                float p3 = __uint_as_float(f2tf32(expf_fast(sacc[nt][3] - mx1)));
                s0 += p0 + p1; s1 += p2 + p3;
                sacc[nt][0] = p0; sacc[nt][1] = p1; sacc[nt][2] = p2; sacc[nt][3] = p3;
            }
            s0 += __shfl_xor_sync(0xffffffffu, s0, 1);
            s0 += __shfl_xor_sync(0xffffffffu, s0, 2);
            s1 += __shfl_xor_sync(0xffffffffu, s1, 1);
            s1 += __shfl_xor_sync(0xffffffffu, s1, 2);
            if (tig == 0) {
                sSum[role * 128 + wm + gid]     = s0;
                sSum[role * 128 + wm + gid + 8] = s1;
            }
            PAIRBAR(barid);
            s0 += sSum[(1 - role) * 128 + wm + gid];
            s1 += sSum[(1 - role) * 128 + wm + gid + 8];
            l0r = l0r * a0 + s0;
            l1r = l1r * a1 + s1;
            #pragma unroll
            for (int nt = 0; nt < 8; nt++) {
                acc[nt][0] *= a0; acc[nt][1] *= a0;
                acc[nt][2] *= a1; acc[nt][3] *= a1;
            }

            // ---- store P fragments to smem: P[pair][gid][k] pairs (r0,r1) ----
            #pragma unroll
            for (int nt = 0; nt < 4; nt++) {
                int c = kh + nt * 8 + tig * 2;
                uint32_t addr = smb + (FP_OFF + pair * 1088 + gid * 136 + 2 * c) * 4;
                STS128(addr,
                       __float_as_uint(sacc[nt][0]), __float_as_uint(sacc[nt][2]),
                       __float_as_uint(sacc[nt][1]), __float_as_uint(sacc[nt][3]));
            }
        }

        // ---- wait V[j] (exact); block sync also publishes P across pair ----
        if (more) { CPW1(); } else { CPW0(); }
        __syncthreads();

        if (active) {
            // ---- PV over own d-half, full 64 k ----
            #pragma unroll
            for (int kb = 0; kb < 8; kb++) {
                const int pidx = pair * 544 + gid * 68 + kb * 8 + tig;
                uint2 pa = P2[pidx];
                uint2 pb = P2[pidx + 4];
                uint32_t a[4] = {pa.x, pa.y, pb.x, pb.y};
                const int vrow = (kb * 4 + tig) * 132;
                #pragma unroll
                for (int nt = 0; nt < 8; nt++) {
                    uint2 vv = V2[vrow + (role * 8 + nt) * 8 + gid];
                    uint32_t bfr[2] = {vv.x, vv.y};
                    mma8(acc[nt], a, bfr);
                }
            }
        }
        __syncthreads();         // V (and P) consumed before refill

        if (more) {
            const float* vs2 = vsrc + (size_t)(k0 + 64) * 128;
            #pragma unroll
            for (int c = 0; c < 4; c++) CPA16(vdst + c * 16, vs2 + c * 4);
            CPC();
        }
    }

    // ---- epilogue: each warp writes its 16 rows x own 64-d half, tf32-rounded
    const float inv0 = 1.0f / l0r;
    const float inv1 = 1.0f / l1r;
    const int gr0 = q0 + wm + gid;
    const int gr1 = gr0 + 8;
    #pragma unroll
    for (int nt = 0; nt < 8; nt++) {
        int c0 = role * 64 + nt * 8 + tig * 2;
        float* o0 = g_ctx + (((size_t)b * TSEQ + gr0) * NH + h) * DH + c0;
        float* o1 = g_ctx + (((size_t)b * TSEQ + gr1) * NH + h) * DH + c0;
        *(float2*)o0 = make_float2(__uint_as_float(f2tf32(acc[nt][0] * inv0)),
                                   __uint_as_float(f2tf32(acc[nt][1] * inv0)));
        *(float2*)o1 = make_float2(__uint_as_float(f2tf32(acc[nt][2] * inv1)),
                                   __uint_as_float(f2tf32(acc[nt][3] * inv1)));
    }
}

// ---------------- launch ------------------------------------------------------
extern "C" void kernel_launch(void* const* d_in, const int* in_sizes, int n_in,
                              void* d_out, int out_size) {
    const float* x   = (const float*)d_in[0];
    const float* wq  = (const float*)d_in[1];
    const float* wk  = (const float*)d_in[2];
    const float* wv  = (const float*)d_in[3];
    const float* wo  = (const float*)d_in[4];
    const float* qnw = (const float*)d_in[5];
    const float* knw = (const float*)d_in[6];
    float* out = (float*)d_out;

    float *qkv_p, *ctx_p, *xt_p, *wt_p, *wot_p;
    cudaGetSymbolAddress((void**)&qkv_p, g_qkv);
    cudaGetSymbolAddress((void**)&ctx_p, g_ctx);
    cudaGetSymbolAddress((void**)&xt_p, g_xt);
    cudaGetSymbolAddress((void**)&wt_p, g_wt);
    cudaGetSymbolAddress((void**)&wot_p, g_wot);

    build_rope_kernel<<<TSEQ, 64>>>();

    // pre-round operands to tf32 (removes cvt from GEMM hot loops)
    tf32_round_kernel<<<8192, 256>>>(x,  xt_p,  MROWS * DMODEL / 4);
    tf32_round_kernel<<<4096, 256>>>(wq, wt_p,                2048 * DMODEL / 4);
    tf32_round_kernel<<<2048, 256>>>(wk, wt_p + 2048 * DMODEL, 1024 * DMODEL / 4);
    tf32_round_kernel<<<2048, 256>>>(wv, wt_p + 3072 * DMODEL, 1024 * DMODEL / 4);
    tf32_round_kernel<<<4096, 256>>>(wo, wot_p,               DMODEL * DMODEL / 4);

    cudaFuncSetAttribute(gemm_kernel,
                         cudaFuncAttributeMaxDynamicSharedMemorySize, GEMM_SMEM);

    // merged QKV projection: N = 4096 (q 2048 | k 1024 | v 1024)
    gemm_kernel<<<dim3(32, 16), 512, GEMM_SMEM>>>(xt_p, wt_p,
                                                  wt_p + 2048 * DMODEL,
                                                  wt_p + 3072 * DMODEL,
                                                  2048, 3072, qkv_p, 4096);

    qkv_postprocess_kernel<<<16384, 256>>>(qnw, knw);

    cudaFuncSetAttribute(flash_attn_kernel,
                         cudaFuncAttributeMaxDynamicSharedMemorySize, FLASH_SMEM);
    flash_attn_kernel<<<dim3(TSEQ / 128, BQ * NH), 512, FLASH_SMEM>>>();

    // output projection (ctx already tf32-rounded by flash epilogue)
    gemm_kernel<<<dim3(16, 16), 512, GEMM_SMEM>>>(ctx_p, wot_p, wot_p, wot_p,
                                                  1 << 30, 1 << 30, out, DMODEL);
}

// round 17
// speedup vs baseline: 1.6322x; 1.0202x over previous
#include <cuda_runtime.h>
#include <math.h>
#include <stdint.h>

// Problem constants
#define BQ   2
#define TSEQ 2048
#define DMODEL 2048
#define NH   16
#define NKV  8
#define DH   128
#define MROWS (BQ*TSEQ)   // 4096

// ---------------- device scratch ----------------------------------------------
__device__ float g_qkv[MROWS * 4096];         // q(2048) | k(1024) | v(1024)
// g_q/g_k: [B,H,T,DH] with d-words permuted within 8-blocks: pos = 2*(d&3) + ((d>>2)&1)
__device__ float g_q  [BQ * NH  * TSEQ * DH]; // tf32 bits, pre-scaled by 1/sqrt(128)
__device__ float g_k  [BQ * NKV * TSEQ * DH]; // tf32 bits
// g_v: [B,Hkv] pair-grouped: word ((t>>3)*4 + (t&3))*256 + d*2 + ((t>>2)&1)
__device__ float g_v  [BQ * NKV * TSEQ * DH]; // tf32 bits
__device__ float g_ctx[MROWS * DMODEL];       // tf32 bits, k-permuted within 8-blocks
__device__ float g_cos[TSEQ * 64];
__device__ float g_sin[TSEQ * 64];
// tf32-pre-rounded, k-permuted operands for the GEMMs
__device__ float g_xt  [MROWS * DMODEL];
__device__ float g_wt  [4096 * DMODEL];       // wq(2048) | wk(1024) | wv(1024)
__device__ float g_wot [DMODEL * DMODEL];

// ---------------- helpers -----------------------------------------------------
__device__ __forceinline__ uint32_t f2tf32(float f) {
    uint32_t u;
    asm("cvt.rna.tf32.f32 %0, %1;" : "=r"(u) : "f"(f));
    return u;
}
__device__ __forceinline__ uint32_t smem_u32(const void* p) {
    uint32_t a;
    asm("{ .reg .u64 t; cvta.to.shared.u64 t, %1; cvt.u32.u64 %0, t; }" : "=r"(a) : "l"(p));
    return a;
}
// D += A(m16k8 row) * B(k8n8 col), tf32
__device__ __forceinline__ void mma8(float* d, const uint32_t* a, const uint32_t* b) {
    asm volatile(
        "mma.sync.aligned.m16n8k8.row.col.f32.tf32.tf32.f32 "
        "{%0,%1,%2,%3}, {%4,%5,%6,%7}, {%8,%9}, {%0,%1,%2,%3};"
        : "+f"(d[0]), "+f"(d[1]), "+f"(d[2]), "+f"(d[3])
        : "r"(a[0]), "r"(a[1]), "r"(a[2]), "r"(a[3]), "r"(b[0]), "r"(b[1]));
}
#define CPA16(dst, src) asm volatile("cp.async.cg.shared.global [%0], [%1], 16;" :: "r"(dst), "l"(src) : "memory")
#define CPC()   asm volatile("cp.async.commit_group;" ::: "memory")
#define CPW0()  asm volatile("cp.async.wait_group 0;" ::: "memory")
#define CPW1()  asm volatile("cp.async.wait_group 1;" ::: "memory")
#define CPW2()  asm volatile("cp.async.wait_group 2;" ::: "memory")
#define PAIRBAR(id) asm volatile("bar.sync %0, 64;" :: "r"(id) : "memory")
#define STS128(addr, v0, v1, v2, v3) \
    asm volatile("st.shared.v4.b32 [%0], {%1,%2,%3,%4};" \
                 :: "r"(addr), "r"(v0), "r"(v1), "r"(v2), "r"(v3) : "memory")

// fast exp on the fma/alu pipes: x <= 0 expected
__device__ __forceinline__ float expf_fast(float x) {
    float z = x * 1.4426950408889634f;
    z = fmaxf(z, -126.0f);
    float r = z + 12582912.0f;                       // round-to-nearest integer
    int   i = __float_as_int(r) - 0x4B400000;
    float f = z - (r - 12582912.0f);                 // f in [-0.5, 0.5]
    float p = fmaf(f, 0.0013333558f, 0.0096181291f); // 2^f poly (deg 5)
    p = fmaf(f, p, 0.0555041087f);
    p = fmaf(f, p, 0.2402265069f);
    p = fmaf(f, p, 0.6931471806f);
    p = fmaf(f, p, 1.0f);
    return __int_as_float(__float_as_int(p) + (i << 23));
}

// ---------------- RoPE table --------------------------------------------------
__global__ void build_rope_kernel() {
    int t = blockIdx.x;
    int i = threadIdx.x;  // 0..63
    double inv = exp(-((double)(2 * i) / 128.0) * log(1.0e6));
    float af = (float)((double)t * inv);
    g_cos[t * 64 + i] = cosf(af);
    g_sin[t * 64 + i] = sinf(af);
}

// ---------------- tf32 pre-round + k-permute copy -----------------------------
// Within each 8-word block: pos = 2*(k&3) + ((k>>2)&1)
// out0 = {k0,k4,k1,k5}, out1 = {k2,k6,k3,k7}  (all tf32-rounded)
__global__ __launch_bounds__(256) void tf32_round_permute_kernel(
    const float* __restrict__ src, float* __restrict__ dst, int n8)
{
    int i = blockIdx.x * 256 + threadIdx.x;
    if (i < n8) {
        float4 v0 = ((const float4*)src)[i * 2];
        float4 v1 = ((const float4*)src)[i * 2 + 1];
        uint4 o0, o1;
        o0.x = f2tf32(v0.x); o0.y = f2tf32(v1.x);
        o0.z = f2tf32(v0.y); o0.w = f2tf32(v1.y);
        o1.x = f2tf32(v0.z); o1.y = f2tf32(v1.z);
        o1.z = f2tf32(v0.w); o1.w = f2tf32(v1.w);
        ((uint4*)dst)[i * 2]     = o0;
        ((uint4*)dst)[i * 2 + 1] = o1;
    }
}

// ---------------- TF32 GEMM: C[m,n] = A[M,K] @ W[N,K]^T -----------------------
// 256x128 tile, BK=16, 4-stage cp.async, 512 threads (16 warps), warp tile 64x32.
// Operands pre-rounded + k-permuted: all fragment fetches are LDS.64.
#define GBM 256
#define GBN 128
#define GBK 16
#define GP  24                          // pitch; 24 mod 32 -> conflict-free uint2
#define GSTG 4
#define GA_WORDS (GBM * GP)             // 6144
#define GB_WORDS (GBN * GP)             // 3072
#define GSTG_WORDS (GA_WORDS + GB_WORDS)
#define GEMM_SMEM (GSTG * GSTG_WORDS * 4)   // 147456 B

__global__ __launch_bounds__(512, 1) void gemm_kernel(
    const float* __restrict__ A, const float* __restrict__ W0,
    const float* __restrict__ W1, const float* __restrict__ W2,
    int ns1, int ns2, float* __restrict__ C, int ldc)
{
    extern __shared__ float gs[];
    const int tid = threadIdx.x, lane = tid & 31, wid = tid >> 5;
    const int gid = lane >> 2, tig = lane & 3;
    const int wm = (wid & 3) * 64, wn = (wid >> 2) * 32;
    const int m0 = blockIdx.y * GBM;
    const int n0 = blockIdx.x * GBN;
    const int K = DMODEL;

    const float* Bw; int nb;
    if (n0 < ns1)      { Bw = W0; nb = n0; }
    else if (n0 < ns2) { Bw = W1; nb = n0 - ns1; }
    else               { Bw = W2; nb = n0 - ns2; }

    // loaders: A row tid>>1, half (tid&1)*8; B row tid>>2, quarter (tid&3)*4
    const int arow = tid >> 1, akseg = (tid & 1) * 8;
    const int brow = tid >> 2, bkseg = (tid & 3) * 4;
    const float* asrc = A  + (size_t)(m0 + arow) * K + akseg;
    const float* bsrc = Bw + (size_t)(nb + brow) * K + bkseg;
    const uint32_t smb = smem_u32(gs);
    const uint32_t adst = smb + (arow * GP + akseg) * 4;
    const uint32_t bdst = smb + (GA_WORDS + brow * GP + bkseg) * 4;

    const int niter = K / GBK;  // 128

    #pragma unroll
    for (int s = 0; s < GSTG - 1; s++) {
        const int k0 = s * GBK;
        const uint32_t so = s * GSTG_WORDS * 4;
        CPA16(adst + so,      asrc + k0);
        CPA16(adst + so + 16, asrc + k0 + 4);
        CPA16(bdst + so,      bsrc + k0);
        CPC();
    }

    float acc[4][4][4];
    #pragma unroll
    for (int mt = 0; mt < 4; mt++)
        #pragma unroll
        for (int nt = 0; nt < 4; nt++)
            #pragma unroll
            for (int r = 0; r < 4; r++) acc[mt][nt][r] = 0.f;

    const uint2* gs2 = (const uint2*)gs;

    for (int kt = 0; kt < niter; kt++) {
        if (kt + 3 <= niter) { CPW2(); }
        else if (kt + 2 == niter) { CPW1(); }
        else { CPW0(); }
        __syncthreads();

        if (kt + 3 < niter) {
            const int k0 = (kt + 3) * GBK;
            const uint32_t so = ((kt + 3) & 3) * GSTG_WORDS * 4;
            CPA16(adst + so,      asrc + k0);
            CPA16(adst + so + 16, asrc + k0 + 4);
            CPA16(bdst + so,      bsrc + k0);
            CPC();
        }

        const uint2* sa2 = gs2 + (kt & 3) * (GSTG_WORDS / 2);
        const uint2* sb2 = sa2 + GA_WORDS / 2;
        #pragma unroll
        for (int ks = 0; ks < 2; ks++) {
            uint32_t af[4][4], bf[4][2];
            #pragma unroll
            for (int mt = 0; mt < 4; mt++) {
                int base = ((wm + mt * 16 + gid) * GP + ks * 8 + tig * 2) >> 1;
                uint2 qa = sa2[base];
                uint2 qb = sa2[base + (8 * GP) / 2];
                af[mt][0] = qa.x; af[mt][2] = qa.y;
                af[mt][1] = qb.x; af[mt][3] = qb.y;
            }
            #pragma unroll
            for (int nt = 0; nt < 4; nt++) {
                int base = ((wn + nt * 8 + gid) * GP + ks * 8 + tig * 2) >> 1;
                uint2 kb = sb2[base];
                bf[nt][0] = kb.x; bf[nt][1] = kb.y;
            }
            #pragma unroll
            for (int mt = 0; mt < 4; mt++)
                #pragma unroll
                for (int nt = 0; nt < 4; nt++)
                    mma8(acc[mt][nt], af[mt], bf[nt]);
        }
    }

    #pragma unroll
    for (int mt = 0; mt < 4; mt++) {
        #pragma unroll
        for (int nt = 0; nt < 4; nt++) {
            int r0 = m0 + wm + mt * 16 + gid;
            int c0 = n0 + wn + nt * 8 + tig * 2;
            *(float2*)&C[(size_t)r0 * ldc + c0]       = make_float2(acc[mt][nt][0], acc[mt][nt][1]);
            *(float2*)&C[(size_t)(r0 + 8) * ldc + c0] = make_float2(acc[mt][nt][2], acc[mt][nt][3]);
        }
    }
}

// ---------------- RMSNorm + RoPE (warp per head), permuted stores -------------
__global__ __launch_bounds__(256) void qkv_postprocess_kernel(
    const float* __restrict__ qnw, const float* __restrict__ knw)
{
    const int lane = threadIdx.x & 31;
    const int hidx = blockIdx.x * 8 + (threadIdx.x >> 5);
    const int tg = hidx >> 5;            // b*T + t
    const int hh = hidx & 31;
    const int b = tg / TSEQ;
    const int t = tg - b * TSEQ;

    const float* src;
    float* dst;
    const float* w = qnw;
    bool isv = false;
    float outscale = 0.08838834764831845f;
    if (hh < NH) {
        src = g_qkv + (size_t)tg * 4096 + hh * DH;
        dst = g_q + ((size_t)(b * NH + hh) * TSEQ + t) * DH;
    } else if (hh < NH + NKV) {
        int h = hh - NH;
        src = g_qkv + (size_t)tg * 4096 + 2048 + h * DH;
        w = knw;
        outscale = 1.0f;
        dst = g_k + ((size_t)(b * NKV + h) * TSEQ + t) * DH;
    } else {
        int h = hh - NH - NKV;
        src = g_qkv + (size_t)tg * 4096 + 3072 + h * DH;
        dst = g_v + (size_t)(b * NKV + h) * (TSEQ * DH)
                  + ((size_t)((t >> 3) * 4 + (t & 3))) * 256 + ((t >> 2) & 1);
        isv = true;
    }

    const int d0 = lane * 4;
    float4 x = *(const float4*)(src + d0);

    if (isv) {
        dst[(d0 + 0) * 2] = __uint_as_float(f2tf32(x.x));
        dst[(d0 + 1) * 2] = __uint_as_float(f2tf32(x.y));
        dst[(d0 + 2) * 2] = __uint_as_float(f2tf32(x.z));
        dst[(d0 + 3) * 2] = __uint_as_float(f2tf32(x.w));
        return;
    }

    float ss = x.x * x.x + x.y * x.y + x.z * x.z + x.w * x.w;
    #pragma unroll
    for (int o = 16; o > 0; o >>= 1) ss += __shfl_xor_sync(0xffffffffu, ss, o);
    const float rms = rsqrtf(ss * (1.0f / 128.0f) + 1e-6f);

    float4 wv = *(const float4*)(w + d0);
    float4 nx;
    nx.x = x.x * rms * wv.x; nx.y = x.y * rms * wv.y;
    nx.z = x.z * rms * wv.z; nx.w = x.w * rms * wv.w;

    float4 pn;
    pn.x = __shfl_xor_sync(0xffffffffu, nx.x, 16);
    pn.y = __shfl_xor_sync(0xffffffffu, nx.y, 16);
    pn.z = __shfl_xor_sync(0xffffffffu, nx.z, 16);
    pn.w = __shfl_xor_sync(0xffffffffu, nx.w, 16);
    const float sgn = (lane < 16) ? -1.0f : 1.0f;

    const int i0 = d0 & 63;
    float4 c4 = *(const float4*)(g_cos + t * 64 + i0);
    float4 s4 = *(const float4*)(g_sin + t * 64 + i0);

    float o0 = (nx.x * c4.x + sgn * pn.x * s4.x) * outscale;
    float o1 = (nx.y * c4.y + sgn * pn.y * s4.y) * outscale;
    float o2 = (nx.z * c4.z + sgn * pn.z * s4.z) * outscale;
    float o3 = (nx.w * c4.w + sgn * pn.w * s4.w) * outscale;

    float* pd = dst + (lane >> 1) * 8 + (lane & 1);
    pd[0] = __uint_as_float(f2tf32(o0));
    pd[2] = __uint_as_float(f2tf32(o1));
    pd[4] = __uint_as_float(f2tf32(o2));
    pd[6] = __uint_as_float(f2tf32(o3));
}

// ---------------- Flash attention v6: 128q tile, d-split pairs, P via smem ----
#define FQ_OFF  0
#define FK_OFF  17408                 // Q: 128*136
#define FV_OFF  (FK_OFF + 8704)      // K: 64*136
#define FP_OFF  (FV_OFF + 8448)      // V: 32*264
#define FEX_OFF (FP_OFF + 8704)      // P: 8 pairs * 8 * 136
#define FLASH_WORDS (FEX_OFF + 512)
#define FLASH_SMEM (FLASH_WORDS * 4) // 175104 B

__global__ __launch_bounds__(512, 1) void flash_attn_kernel() {
    extern __shared__ float fsm[];
    const uint2* Q2 = (const uint2*)fsm;                 // pitch 68 uint2
    const uint2* K2 = (const uint2*)(fsm + FK_OFF);
    const uint2* V2 = (const uint2*)(fsm + FV_OFF);
    const uint2* P2 = (const uint2*)(fsm + FP_OFF);
    float* sMax = fsm + FEX_OFF;        // [2][128]
    float* sSum = fsm + FEX_OFF + 256;  // [2][128]

    const int tid  = threadIdx.x;
    const int lane = tid & 31;
    const int wid  = tid >> 5;           // 0..15
    const int gid  = lane >> 2;
    const int tig  = lane & 3;
    const int pair = wid & 7;
    const int role = wid >> 3;           // 0/1: k-half in S, d-half in PV
    const int wm   = pair * 16;
    const int kh   = role * 32;
    const int barid = pair + 1;

    const int bh = blockIdx.y;
    const int b = bh >> 4;
    const int h = bh & 15;
    const int hk = h >> 1;
    const int q0 = (15 - (int)blockIdx.x) * 128;   // big blocks first
    const int ntiles = (q0 >> 6) + 2;

    const float* Qg = g_q + ((size_t)(b * NH + h) * TSEQ + q0) * DH;
    const float* Kg = g_k + (size_t)(b * NKV + hk) * TSEQ * DH;
    const float* Vg = g_v + (size_t)(b * NKV + hk) * (TSEQ * DH);

    // cp.async loader geometry (512 threads)
    const uint32_t smb = smem_u32(fsm);
    const int qr = tid >> 2, qs = (tid & 3) * 32;        // Q: 128 rows
    const uint32_t qdst = smb + (qr * 136 + qs) * 4;
    const float* qsrc = Qg + (size_t)qr * DH + qs;
    const int kr = tid >> 3, ksg = (tid & 7) * 16;       // K: 64 rows
    const uint32_t kdst = smb + (FK_OFF + kr * 136 + ksg) * 4;
    const float* ksrc = Kg + (size_t)kr * DH + ksg;
    const int vgr = tid >> 4, vsg = (tid & 15) * 16;     // V: 32 groups
    const uint32_t vdst = smb + (FV_OFF + vgr * 264 + vsg) * 4;
    const float* vsrc = Vg + vgr * 256 + vsg;

    // prologue: {Q + K[0]} group, {V[0]} group
    #pragma unroll
    for (int c = 0; c < 8; c++) CPA16(qdst + c * 16, qsrc + c * 4);
    #pragma unroll
    for (int c = 0; c < 4; c++) CPA16(kdst + c * 16, ksrc + c * 4);
    CPC();
    #pragma unroll
    for (int c = 0; c < 4; c++) CPA16(vdst + c * 16, vsrc + c * 4);
    CPC();

    float acc[8][4];                      // PV for own d-half (full k)
    #pragma unroll
    for (int nt = 0; nt < 8; nt++)
        #pragma unroll
        for (int r = 0; r < 4; r++) acc[nt][r] = 0.f;
    float m0r = -INFINITY, m1r = -INFINITY, l0r = 0.f, l1r = 0.f;

    const int pr0 = wm + gid, pr1 = pr0 + 8;   // pair-local q rows (block view)

    for (int j = 0; j < ntiles; j++) {
        const int k0 = j * 64;
        const bool more = (j + 1 < ntiles);
        const bool active = (q0 + wm + 15) >= k0;

        CPW1();                  // K[j] (+Q) resident; V[j] may be pending
        __syncthreads();

        // ---- S = Q @ K^T over own k-half (16 x 32) ----
        float sacc[4][4];
        #pragma unroll
        for (int nt = 0; nt < 4; nt++)
            #pragma unroll
            for (int r = 0; r < 4; r++) sacc[nt][r] = 0.f;

        if (active) {
            #pragma unroll
            for (int ks = 0; ks < 16; ks++) {
                uint32_t af[4];
                const int qo = ((wm + gid) * 136 + ks * 8 + tig * 2) >> 1;
                uint2 qa = Q2[qo];
                uint2 qb = Q2[qo + 8 * 68];
                af[0] = qa.x; af[2] = qa.y;
                af[1] = qb.x; af[3] = qb.y;
                #pragma unroll
                for (int nt = 0; nt < 4; nt++) {
                    uint2 kb2 = K2[((kh + nt * 8 + gid) * 136 + ks * 8 + tig * 2) >> 1];
                    uint32_t bfr[2] = {kb2.x, kb2.y};
                    mma8(sacc[nt], af, bfr);
                }
            }
        }
        __syncthreads();         // K consumed by all

        if (more) {
            const float* ks2 = ksrc + (size_t)(k0 + 64) * DH;
            #pragma unroll
            for (int c = 0; c < 4; c++) CPA16(kdst + c * 16, ks2 + c * 4);
            CPC();
        }

        if (active) {
            // ---- mask near-diagonal tiles ----
            const int off = q0 - k0;    // mask if local col c0 > off + row
            if (off < 64) {
                #pragma unroll
                for (int nt = 0; nt < 4; nt++) {
                    int c0 = kh + nt * 8 + tig * 2;
                    if (c0     > off + pr0) sacc[nt][0] = -1e30f;
                    if (c0 + 1 > off + pr0) sacc[nt][1] = -1e30f;
                    if (c0     > off + pr1) sacc[nt][2] = -1e30f;
                    if (c0 + 1 > off + pr1) sacc[nt][3] = -1e30f;
                }
            }

            // ---- partial max + pair exchange ----
            float mx0 = -INFINITY, mx1 = -INFINITY;
            #pragma unroll
            for (int nt = 0; nt < 4; nt++) {
                mx0 = fmaxf(mx0, fmaxf(sacc[nt][0], sacc[nt][1]));
                mx1 = fmaxf(mx1, fmaxf(sacc[nt][2], sacc[nt][3]));
            }
            mx0 = fmaxf(mx0, __shfl_xor_sync(0xffffffffu, mx0, 1));
            mx0 = fmaxf(mx0, __shfl_xor_sync(0xffffffffu, mx0, 2));
            mx1 = fmaxf(mx1, __shfl_xor_sync(0xffffffffu, mx1, 1));
            mx1 = fmaxf(mx1, __shfl_xor_sync(0xffffffffu, mx1, 2));
            if (tig == 0) {
                sMax[role * 128 + wm + gid]     = mx0;
                sMax[role * 128 + wm + gid + 8] = mx1;
            }
            PAIRBAR(barid);
            mx0 = fmaxf(fmaxf(mx0, sMax[(1 - role) * 128 + wm + gid]),     m0r);
            mx1 = fmaxf(fmaxf(mx1, sMax[(1 - role) * 128 + wm + gid + 8]), m1r);
            const float a0 = expf_fast(m0r - mx0);
            const float a1 = expf_fast(m1r - mx1);
            m0r = mx0; m1r = mx1;

            // ---- exp own cols + pair sum exchange ----
            float s0 = 0.f, s1 = 0.f;
            #pragma unroll
            for (int nt = 0; nt < 4; nt++) {
                float p0 = __uint_as_float(f2tf32(expf_fast(sacc[nt][0] - mx0)));
                float p1 = __uint_as_float(f2tf32(expf_fast(sacc[nt][1] - mx0)));
                float p2 = __uint_as_float(f2tf32(expf_fast(sacc[nt][2] - mx1)));
                float p3 = __uint_as_float(f2tf32(expf_fast(sacc[nt][3] - mx1)));
                s0 += p0 + p1; s1 += p2 + p3;
                sacc[nt][0] = p0; sacc[nt][1] = p1; sacc[nt][2] = p2; sacc[nt][3] = p3;
            }
            s0 += __shfl_xor_sync(0xffffffffu, s0, 1);
            s0 += __shfl_xor_sync(0xffffffffu, s0, 2);
            s1 += __shfl_xor_sync(0xffffffffu, s1, 1);
            s1 += __shfl_xor_sync(0xffffffffu, s1, 2);
            if (tig == 0) {
                sSum[role * 128 + wm + gid]     = s0;
                sSum[role * 128 + wm + gid + 8] = s1;
            }
            PAIRBAR(barid);
            s0 += sSum[(1 - role) * 128 + wm + gid];
            s1 += sSum[(1 - role) * 128 + wm + gid + 8];
            l0r = l0r * a0 + s0;
            l1r = l1r * a1 + s1;
            #pragma unroll
            for (int nt = 0; nt < 8; nt++) {
                acc[nt][0] *= a0; acc[nt][1] *= a0;
                acc[nt][2] *= a1; acc[nt][3] *= a1;
            }

            // ---- store P fragments to smem: P[pair][gid][k] pairs (r0,r1) ----
            #pragma unroll
            for (int nt = 0; nt < 4; nt++) {
                int c = kh + nt * 8 + tig * 2;
                uint32_t addr = smb + (FP_OFF + pair * 1088 + gid * 136 + 2 * c) * 4;
                STS128(addr,
                       __float_as_uint(sacc[nt][0]), __float_as_uint(sacc[nt][2]),
                       __float_as_uint(sacc[nt][1]), __float_as_uint(sacc[nt][3]));
            }
        }

        // ---- wait V[j] (exact); block sync also publishes P across pair ----
        if (more) { CPW1(); } else { CPW0(); }
        __syncthreads();

        if (active) {
            // ---- PV over own d-half, full 64 k ----
            #pragma unroll
            for (int kb = 0; kb < 8; kb++) {
                const int pidx = pair * 544 + gid * 68 + kb * 8 + tig;
                uint2 pa = P2[pidx];
                uint2 pb = P2[pidx + 4];
                uint32_t a[4] = {pa.x, pa.y, pb.x, pb.y};
                const int vrow = (kb * 4 + tig) * 132;
                #pragma unroll
                for (int nt = 0; nt < 8; nt++) {
                    uint2 vv = V2[vrow + (role * 8 + nt) * 8 + gid];
                    uint32_t bfr[2] = {vv.x, vv.y};
                    mma8(acc[nt], a, bfr);
                }
            }
        }
        __syncthreads();         // V (and P) consumed before refill

        if (more) {
            const float* vs2 = vsrc + (size_t)(k0 + 64) * 128;
            #pragma unroll
            for (int c = 0; c < 4; c++) CPA16(vdst + c * 16, vs2 + c * 4);
            CPC();
        }
    }

    // ---- epilogue: 16 rows x own 64-d half, tf32-rounded, k-permuted ctx ----
    const float inv0 = 1.0f / l0r;
    const float inv1 = 1.0f / l1r;
    const int gr0 = q0 + wm + gid;
    const int gr1 = gr0 + 8;
    const int cA = tig * 2, cB = tig * 2 + 1;
    const int posA = 2 * (cA & 3) + (cA >> 2);
    const int posB = 2 * (cB & 3) + (cB >> 2);
    #pragma unroll
    for (int nt = 0; nt < 8; nt++) {
        int base8 = role * 64 + nt * 8;
        float* o0 = g_ctx + (((size_t)b * TSEQ + gr0) * NH + h) * DH + base8;
        float* o1 = g_ctx + (((size_t)b * TSEQ + gr1) * NH + h) * DH + base8;
        o0[posA] = __uint_as_float(f2tf32(acc[nt][0] * inv0));
        o0[posB] = __uint_as_float(f2tf32(acc[nt][1] * inv0));
        o1[posA] = __uint_as_float(f2tf32(acc[nt][2] * inv1));
        o1[posB] = __uint_as_float(f2tf32(acc[nt][3] * inv1));
    }
}

// ---------------- launch ------------------------------------------------------
extern "C" void kernel_launch(void* const* d_in, const int* in_sizes, int n_in,
                              void* d_out, int out_size) {
    const float* x   = (const float*)d_in[0];
    const float* wq  = (const float*)d_in[1];
    const float* wk  = (const float*)d_in[2];
    const float* wv  = (const float*)d_in[3];
    const float* wo  = (const float*)d_in[4];
    const float* qnw = (const float*)d_in[5];
    const float* knw = (const float*)d_in[6];
    float* out = (float*)d_out;

    float *qkv_p, *ctx_p, *xt_p, *wt_p, *wot_p;
    cudaGetSymbolAddress((void**)&qkv_p, g_qkv);
    cudaGetSymbolAddress((void**)&ctx_p, g_ctx);
    cudaGetSymbolAddress((void**)&xt_p, g_xt);
    cudaGetSymbolAddress((void**)&wt_p, g_wt);
    cudaGetSymbolAddress((void**)&wot_p, g_wot);

    build_rope_kernel<<<TSEQ, 64>>>();

    // pre-round + k-permute operands (GEMM fragments become LDS.64)
    tf32_round_permute_kernel<<<4096, 256>>>(x,  xt_p,  MROWS * DMODEL / 8);
    tf32_round_permute_kernel<<<2048, 256>>>(wq, wt_p,                2048 * DMODEL / 8);
    tf32_round_permute_kernel<<<1024, 256>>>(wk, wt_p + 2048 * DMODEL, 1024 * DMODEL / 8);
    tf32_round_permute_kernel<<<1024, 256>>>(wv, wt_p + 3072 * DMODEL, 1024 * DMODEL / 8);
    tf32_round_permute_kernel<<<2048, 256>>>(wo, wot_p,               DMODEL * DMODEL / 8);

    cudaFuncSetAttribute(gemm_kernel,
                         cudaFuncAttributeMaxDynamicSharedMemorySize, GEMM_SMEM);

    // merged QKV projection: N = 4096 (q 2048 | k 1024 | v 1024)
    gemm_kernel<<<dim3(32, 16), 512, GEMM_SMEM>>>(xt_p, wt_p,
                                                  wt_p + 2048 * DMODEL,
                                                  wt_p + 3072 * DMODEL,
                                                  2048, 3072, qkv_p, 4096);

    qkv_postprocess_kernel<<<16384, 256>>>(qnw, knw);

    cudaFuncSetAttribute(flash_attn_kernel,
                         cudaFuncAttributeMaxDynamicSharedMemorySize, FLASH_SMEM);
    flash_attn_kernel<<<dim3(TSEQ / 128, BQ * NH), 512, FLASH_SMEM>>>();

    // output projection (ctx already rounded + permuted by flash epilogue)
    gemm_kernel<<<dim3(16, 16), 512, GEMM_SMEM>>>(ctx_p, wot_p, wot_p, wot_p,
                                                  1 << 30, 1 << 30, out, DMODEL);
}